// round 11
// baseline (speedup 1.0000x reference)
#include <cuda_runtime.h>
#include <cstdint>
#include <cstddef>

#define B_      64
#define LQ      1024
#define LK      1024
#define DH      64
#define QT      16
#define CHUNK   128
#define NCH     (LK / CHUNK)   // 8
#define NTHR    512
#define KP32    36             // K smem pitch in u32: bank=(36r+u)%32=(4r+u)%32 -> conflict-free
#define SCP     1028           // sc pitch: score STS conflict-free
#define CAPS    512            // sparsemax compact-list capacity (floats, per warp)
#define CAPG    256            // gather pair capacity (pairs, per warp)
#define TEMP_INV 0.125f
#define REMOVED  (-1.0e30f)
#define CUTV     (-1.0e29f)

// smem: khi[128*36 u32] kmid[128*36 u32] (=9216 floats; reused as 16x576 warp scratch) | sc[16*1028]
#define KS_FLOATS   (2 * CHUNK * KP32)     // 9216
#define SC_FLOATS   (QT * SCP)             // 16448
#define SMEM_FLOATS (KS_FLOATS + SC_FLOATS)
#define SMEM_BYTES  (SMEM_FLOATS * 4)
#define WSCR        576                    // per-warp scratch floats (16*576 = 9216)
#define KMID_BYTE_OFF (CHUNK * KP32 * 4)   // byte offset of kmid_s from khi_s

#define KELEMS  (B_ * LK * DH)             // 4,194,304
#define KU32S   (KELEMS / 2)               // u32 (f16x2) per split array

__device__ int      g_mask_kind;           // 0 = uint8/bool, 1 = int32, 2 = float32
__device__ unsigned g_khi[KU32S];          // K fp16 hi  (f16x2-packed), built per launch
__device__ unsigned g_kmid[KU32S];         // K fp16 mid (residual), built per launch

__global__ void detect_mask_kernel(const unsigned char* __restrict__ m) {
    __shared__ int nz[4];
    int tid = threadIdx.x;
    if (tid < 4) nz[tid] = 0;
    __syncthreads();
    int ph = tid & 3;
    int c = 0;
    for (int i = tid; i < 8192; i += 512)
        if (m[i]) c++;
    if (c) atomicAdd(&nz[ph], c);
    __syncthreads();
    if (tid == 0) {
        int kind;
        if ((nz[1] | nz[2] | nz[3]) == 0)      kind = 1;  // int32
        else if (nz[0] == 0 && nz[3] > 0)      kind = 2;  // float32
        else                                   kind = 0;  // uint8 / bool
        g_mask_kind = kind;
    }
}

// pack two fp32 -> f16x2 (lo = x, hi = y)
__device__ __forceinline__ unsigned pack_h2(float x, float y) {
    unsigned r;
    asm("cvt.rn.f16x2.f32 %0, %1, %2;" : "=r"(r) : "f"(y), "f"(x));
    return r;
}
// unpack f16x2 -> two fp32
__device__ __forceinline__ void unpack_h2(unsigned p, float& x, float& y) {
    asm("{ .reg .f16 l, h; mov.b32 {l, h}, %2; cvt.f32.f16 %0, l; cvt.f32.f16 %1, h; }"
        : "=f"(x), "=f"(y) : "r"(p));
}

// ---- per-launch K split: fp16 hi + mid residual (byte-neutral vs fp32 K) ----
__global__ void split_k_kernel(const float* __restrict__ k) {
    int i = blockIdx.x * 256 + threadIdx.x;        // float4 index
    float4 kv = ((const float4*)k)[i];
    unsigned hA = pack_h2(kv.x, kv.y);
    unsigned hB = pack_h2(kv.z, kv.w);
    float hx, hy, hz, hw;
    unpack_h2(hA, hx, hy);
    unpack_h2(hB, hz, hw);
    unsigned mA = pack_h2(kv.x - hx, kv.y - hy);
    unsigned mB = pack_h2(kv.z - hz, kv.w - hw);
    ((uint2*)g_khi)[i]  = make_uint2(hA, hB);
    ((uint2*)g_kmid)[i] = make_uint2(mA, mB);
}

__device__ __forceinline__ void mma_f16(float& d0, float& d1, float& d2, float& d3,
                                        unsigned a0, unsigned a1, unsigned a2, unsigned a3,
                                        unsigned b0, unsigned b1) {
    asm("mma.sync.aligned.m16n8k16.row.col.f32.f16.f16.f32 "
        "{%0,%1,%2,%3}, {%4,%5,%6,%7}, {%8,%9}, {%0,%1,%2,%3};"
        : "+f"(d0), "+f"(d1), "+f"(d2), "+f"(d3)
        : "r"(a0), "r"(a1), "r"(a2), "r"(a3), "r"(b0), "r"(b1));
}

__device__ __forceinline__ void ldsm_x4(unsigned& r0, unsigned& r1, unsigned& r2, unsigned& r3,
                                        unsigned saddr) {
    asm volatile("ldmatrix.sync.aligned.m8n8.x4.shared.b16 {%0,%1,%2,%3}, [%4];"
                 : "=r"(r0), "=r"(r1), "=r"(r2), "=r"(r3) : "r"(saddr));
}

// --------------------------------------------------------------------------
// One CTA = 16 q-rows of one batch, 512 threads / 16 warps.
// QK^T: fp16x2 3-term compensated MMA (m16n8k16), K pre-split globally.
// Staging = pure uint4 copy; A-fragments via ldmatrix.x4 (1 instr / 16x16).
// Sparsemax: Michelot with survivor compaction. Gather: ballot-compacted
// (p,j) pairs, 4-way MLP batched V loads.
// --------------------------------------------------------------------------
extern "C" __global__ void __launch_bounds__(NTHR, 2)
sparse_attn_kernel(const float* __restrict__ q,
                   const float* __restrict__ v,
                   const void*  __restrict__ maskp,
                   float* __restrict__ out,
                   float* __restrict__ attn,
                   int write_attn)
{
    extern __shared__ float sm[];
    unsigned* khi_s = (unsigned*)sm;              // [CHUNK][KP32] f16x2 (hi)
    float*    sc    = sm + KS_FLOATS;             // [QT][SCP]

    const int tid  = threadIdx.x;
    const int w    = tid >> 5;
    const int lane = tid & 31;
    const int b    = blockIdx.y;
    const int q0   = blockIdx.x * QT;
    const int mkind = g_mask_kind;

    // ---- Q subtile (w>>3) as f16x2 B fragments (hi + mid), 16 regs ----
    unsigned bh0[4], bh1[4], bm0[4], bm1[4];
    {
        const float* qb = q + ((size_t)(b * LQ + q0 + 8 * (w >> 3) + (lane >> 2))) * DH + 2 * (lane & 3);
        #pragma unroll
        for (int ks = 0; ks < 4; ++ks) {
            float2 p0 = *(const float2*)(qb + ks * 16);
            float2 p1 = *(const float2*)(qb + ks * 16 + 8);
            float f0 = p0.x * TEMP_INV, f1 = p0.y * TEMP_INV;
            float f2 = p1.x * TEMP_INV, f3 = p1.y * TEMP_INV;
            bh0[ks] = pack_h2(f0, f1);
            bh1[ks] = pack_h2(f2, f3);
            float h0, h1, h2, h3;
            unpack_h2(bh0[ks], h0, h1);
            unpack_h2(bh1[ks], h2, h3);
            bm0[ks] = pack_h2(f0 - h0, f1 - h1);
            bm1[ks] = pack_h2(f2 - h2, f3 - h3);
        }
    }
    const int kr0 = 16 * (w & 7);

    // ldmatrix per-lane address (shared space), ks advances by 32 bytes
    unsigned lm_base;
    {
        int g  = lane >> 3;                        // matrix index 0..3
        int rl = lane & 7;
        int row = kr0 + rl + 8 * (g & 1);          // m1/m3 -> rows +8
        unsigned sbase = (unsigned)__cvta_generic_to_shared(khi_s);
        lm_base = sbase + (unsigned)(row * KP32 * 4 + (g >> 1) * 16);   // m2/m3 -> k+8
    }

    // ---- QK^T over 8 chunks of 128 K-rows ----
    for (int c = 0; c < NCH; ++c) {
        __syncthreads();
        // stage pre-split K chunk: pure uint4 copy (hi then mid)
        {
            const uint4* ghi = (const uint4*)(g_khi  + (size_t)(b * LK + c * CHUNK) * (DH / 2));
            const uint4* gmi = (const uint4*)(g_kmid + (size_t)(b * LK + c * CHUNK) * (DH / 2));
            #pragma unroll
            for (int it = 0; it < 2; ++it) {
                int fi = tid + NTHR * it;          // 0..1023 uint4 (8 per row)
                int r  = fi >> 3;
                int c4 = fi & 7;
                *(uint4*)(khi_s + r * KP32 + 4 * c4) = ghi[fi];
                *(uint4*)(khi_s + CHUNK * KP32 + r * KP32 + 4 * c4) = gmi[fi];
            }
        }
        __syncthreads();

        float d0 = 0.f, d1 = 0.f, d2 = 0.f, d3 = 0.f;
        #pragma unroll
        for (int ks = 0; ks < 4; ++ks) {
            unsigned ah0, ah1, ah2, ah3, am0, am1, am2, am3;
            ldsm_x4(ah0, ah1, ah2, ah3, lm_base + ks * 32);
            ldsm_x4(am0, am1, am2, am3, lm_base + KMID_BYTE_OFF + ks * 32);
            mma_f16(d0, d1, d2, d3, ah0, ah1, ah2, ah3, bm0[ks], bm1[ks]);  // hi*mid
            mma_f16(d0, d1, d2, d3, am0, am1, am2, am3, bh0[ks], bh1[ks]);  // mid*hi
            mma_f16(d0, d1, d2, d3, ah0, ah1, ah2, ah3, bh0[ks], bh1[ks]);  // hi*hi
        }
        // C 16x8: rows = k, cols = q
        int kg = c * CHUNK + kr0 + (lane >> 2);
        int qc = 8 * (w >> 3) + 2 * (lane & 3);
        sc[qc * SCP + kg]           = d0;
        sc[(qc + 1) * SCP + kg]     = d1;
        sc[qc * SCP + kg + 8]       = d2;
        sc[(qc + 1) * SCP + kg + 8] = d3;
    }
    __syncthreads();

    // ---- mask pass, 16-byte vectorized ----
    {
        size_t mbase = ((size_t)b * LQ + q0) * LK;
        if (mkind == 0) {
            const uint4* m4 = (const uint4*)((const unsigned char*)maskp + mbase);
            #pragma unroll
            for (int it = 0; it < (QT * LK) / 16 / NTHR; ++it) {
                int idx  = tid + NTHR * it;
                uint4 u  = m4[idx];
                int base = idx * 16;
                float* srow = sc + (base >> 10) * SCP + (base & 1023);
                #pragma unroll
                for (int bt = 0; bt < 4; ++bt) {
                    unsigned uu = (&u.x)[bt];
                    if (uu & 0x000000FFu) srow[bt * 4 + 0] = REMOVED;
                    if (uu & 0x0000FF00u) srow[bt * 4 + 1] = REMOVED;
                    if (uu & 0x00FF0000u) srow[bt * 4 + 2] = REMOVED;
                    if (uu & 0xFF000000u) srow[bt * 4 + 3] = REMOVED;
                }
            }
        } else {
            const uint4* m4 = (const uint4*)((const unsigned*)maskp + mbase);
            #pragma unroll
            for (int it = 0; it < (QT * LK) / 4 / NTHR; ++it) {
                int idx  = tid + NTHR * it;
                uint4 u  = m4[idx];
                int base = idx * 4;
                float* srow = sc + (base >> 10) * SCP + (base & 1023);
                if (u.x) srow[0] = REMOVED;
                if (u.y) srow[1] = REMOVED;
                if (u.z) srow[2] = REMOVED;
                if (u.w) srow[3] = REMOVED;
            }
        }
    }
    __syncthreads();   // also fences k_s scratch reuse (GEMM reads done)

    // ---- sparsemax (warp w owns row w): Michelot with survivor compaction ----
    const float* zr = sc + w * SCP;
    float* wsc = sm + w * WSCR;            // per-warp scratch in dead K region
    const unsigned lt = (1u << lane) - 1u;

    float S = 0.0f; int Cl = 0;
    #pragma unroll
    for (int t4 = 0; t4 < 8; ++t4) {
        float4 zv = *(const float4*)(zr + 4 * lane + 128 * t4);
        if (zv.x > CUTV) { S += zv.x; Cl++; }
        if (zv.y > CUTV) { S += zv.y; Cl++; }
        if (zv.z > CUTV) { S += zv.z; Cl++; }
        if (zv.w > CUTV) { S += zv.w; Cl++; }
    }
    #pragma unroll
    for (int o = 16; o; o >>= 1) S += __shfl_xor_sync(0xFFFFFFFFu, S, o);
    int C = __reduce_add_sync(0xFFFFFFFFu, Cl);

    float tau;
    if (C > 0) {
        tau = (S - 1.0f) / (float)C;
        // compacting scan with tau0: survivors -> wsc (support set shrinks monotonically)
        float s2 = 0.0f; int c2l = 0; int cnt = 0;
        #pragma unroll
        for (int t4 = 0; t4 < 8; ++t4) {
            float4 zv = *(const float4*)(zr + 4 * lane + 128 * t4);
            #pragma unroll
            for (int e = 0; e < 4; ++e) {
                float ze = (&zv.x)[e];
                bool a = ze > tau;
                unsigned bb = __ballot_sync(0xFFFFFFFFu, a);
                if (a) {
                    int ps = cnt + __popc(bb & lt);
                    if (ps < CAPS) wsc[ps] = ze;
                    s2 += ze; c2l++;
                }
                cnt += __popc(bb);
            }
        }
        int c2 = __reduce_add_sync(0xFFFFFFFFu, c2l);
        #pragma unroll
        for (int o = 16; o; o >>= 1) s2 += __shfl_xor_sync(0xFFFFFFFFu, s2, o);

        if (c2 != C) {
            if (cnt <= CAPS) {
                __syncwarp();
                S = s2; C = c2;
                tau = (S - 1.0f) / (float)C;
                for (int iter = 0; iter < 64; ++iter) {
                    float s3 = 0.0f; int c3l = 0;
                    for (int i = lane; i < cnt; i += 32) {
                        float z3 = wsc[i];
                        if (z3 > tau) { s3 += z3; c3l++; }
                    }
                    int c3 = __reduce_add_sync(0xFFFFFFFFu, c3l);
                    #pragma unroll
                    for (int o = 16; o; o >>= 1) s3 += __shfl_xor_sync(0xFFFFFFFFu, s3, o);
                    if (c3 == C) break;
                    S = s3; C = c3;
                    tau = (S - 1.0f) / (float)C;
                }
            } else {
                // stateless fallback (huge support)
                S = s2; C = c2;
                tau = (S - 1.0f) / (float)C;
                for (int iter = 0; iter < 64; ++iter) {
                    float s3 = 0.0f; int c3l = 0;
                    #pragma unroll
                    for (int t4 = 0; t4 < 8; ++t4) {
                        float4 zv = *(const float4*)(zr + 4 * lane + 128 * t4);
                        if (zv.x > tau) { s3 += zv.x; c3l++; }
                        if (zv.y > tau) { s3 += zv.y; c3l++; }
                        if (zv.z > tau) { s3 += zv.z; c3l++; }
                        if (zv.w > tau) { s3 += zv.w; c3l++; }
                    }
                    int c3 = __reduce_add_sync(0xFFFFFFFFu, c3l);
                    #pragma unroll
                    for (int o = 16; o; o >>= 1) s3 += __shfl_xor_sync(0xFFFFFFFFu, s3, o);
                    if (c3 == C) break;
                    S = s3; C = c3;
                    tau = (S - 1.0f) / (float)C;
                }
            }
        }
    } else {
        tau = 1.0e30f;                     // fully-masked row
    }
    __syncwarp();

    // ---- probabilities -> attn (float4 stores) + ballot-compacted (p,j) pairs ----
    const float2* vb2 = (const float2*)(v + (size_t)b * LK * DH);
    float* cp = wsc;                       // reuse scratch for (p, j) pairs
    float* arow = attn + ((size_t)(b * LQ + q0 + w)) * LK;
    float2 acc2 = make_float2(0.0f, 0.0f);
    int cnt = 0;

    #pragma unroll
    for (int tt = 0; tt < 8; ++tt) {
        const int j0 = 4 * lane + 128 * tt;
        float4 zv = *(const float4*)(zr + j0);
        float4 pv;
        pv.x = fmaxf(zv.x - tau, 0.0f);
        pv.y = fmaxf(zv.y - tau, 0.0f);
        pv.z = fmaxf(zv.z - tau, 0.0f);
        pv.w = fmaxf(zv.w - tau, 0.0f);
        if (write_attn) *(float4*)(arow + j0) = pv;

        unsigned bb0 = __ballot_sync(0xFFFFFFFFu, pv.x > 0.0f);
        unsigned bb1 = __ballot_sync(0xFFFFFFFFu, pv.y > 0.0f);
        unsigned bb2 = __ballot_sync(0xFFFFFFFFu, pv.z > 0.0f);
        unsigned bb3 = __ballot_sync(0xFFFFFFFFu, pv.w > 0.0f);
        int base0 = cnt;
        int base1 = base0 + __popc(bb0);
        int base2 = base1 + __popc(bb1);
        int base3 = base2 + __popc(bb2);
        cnt       = base3 + __popc(bb3);

        int ps;
        ps = base0 + __popc(bb0 & lt);
        if (pv.x > 0.0f && ps < CAPG) { cp[2 * ps] = pv.x; cp[2 * ps + 1] = __int_as_float(j0); }
        ps = base1 + __popc(bb1 & lt);
        if (pv.y > 0.0f && ps < CAPG) { cp[2 * ps] = pv.y; cp[2 * ps + 1] = __int_as_float(j0 + 1); }
        ps = base2 + __popc(bb2 & lt);
        if (pv.z > 0.0f && ps < CAPG) { cp[2 * ps] = pv.z; cp[2 * ps + 1] = __int_as_float(j0 + 2); }
        ps = base3 + __popc(bb3 & lt);
        if (pv.w > 0.0f && ps < CAPG) { cp[2 * ps] = pv.w; cp[2 * ps + 1] = __int_as_float(j0 + 3); }

        // overflow (support > CAPG): serial fallback for spilled entries
        if (cnt > CAPG) {
            #pragma unroll
            for (int e = 0; e < 4; ++e) {
                float pe = (&pv.x)[e];
                unsigned bb = (e == 0) ? bb0 : (e == 1) ? bb1 : (e == 2) ? bb2 : bb3;
                int be     = (e == 0) ? base0 : (e == 1) ? base1 : (e == 2) ? base2 : base3;
                unsigned ovf = __ballot_sync(0xFFFFFFFFu,
                                             pe > 0.0f && (be + __popc(bb & lt)) >= CAPG);
                while (ovf) {
                    int src = __ffs(ovf) - 1;
                    ovf &= ovf - 1;
                    float pj = __shfl_sync(0xFFFFFFFFu, pe, src);
                    int j = 4 * src + 128 * tt + e;
                    const float2 vv = vb2[j * 32 + lane];
                    acc2.x += pj * vv.x;
                    acc2.y += pj * vv.y;
                }
            }
        }
    }
    __syncwarp();

    // ---- batched V gather: 4 independent loads in flight ----
    {
        const int cn = cnt < CAPG ? cnt : CAPG;
        int i = 0;
        for (; i + 4 <= cn; i += 4) {
            float4 e0 = *(const float4*)(cp + 2 * i);
            float4 e1 = *(const float4*)(cp + 2 * i + 4);
            const float2 v0 = vb2[__float_as_int(e0.y) * 32 + lane];
            const float2 v1 = vb2[__float_as_int(e0.w) * 32 + lane];
            const float2 v2 = vb2[__float_as_int(e1.y) * 32 + lane];
            const float2 v3 = vb2[__float_as_int(e1.w) * 32 + lane];
            acc2.x += e0.x * v0.x;  acc2.y += e0.x * v0.y;
            acc2.x += e0.z * v1.x;  acc2.y += e0.z * v1.y;
            acc2.x += e1.x * v2.x;  acc2.y += e1.x * v2.y;
            acc2.x += e1.z * v3.x;  acc2.y += e1.z * v3.y;
        }
        for (; i < cn; ++i) {
            float p = cp[2 * i];
            int  j  = __float_as_int(cp[2 * i + 1]);
            const float2 vv = vb2[j * 32 + lane];
            acc2.x += p * vv.x;
            acc2.y += p * vv.y;
        }
    }

    *(float2*)(out + ((size_t)(b * LQ + q0 + w)) * DH + 2 * lane) = acc2;
}

// --------------------------------------------------------------------------
extern "C" void kernel_launch(void* const* d_in, const int* in_sizes, int n_in,
                              void* d_out, int out_size) {
    const float* q = (const float*)d_in[0];
    const float* k = (const float*)d_in[1];
    const float* v = (const float*)d_in[2];
    const void*  m = d_in[3];

    float* out = (float*)d_out;
    long long out_elems  = (long long)B_ * LQ * DH;
    long long attn_elems = (long long)B_ * LQ * LK;
    int write_attn = ((long long)out_size >= out_elems + attn_elems) ? 1 : 0;
    float* attn = out + (size_t)out_elems;

    detect_mask_kernel<<<1, 512>>>((const unsigned char*)m);
    split_k_kernel<<<KELEMS / 4 / 256, 256>>>(k);

    cudaFuncSetAttribute(sparse_attn_kernel,
                         cudaFuncAttributeMaxDynamicSharedMemorySize, SMEM_BYTES);

    dim3 grid(LQ / QT, B_);
    sparse_attn_kernel<<<grid, NTHR, SMEM_BYTES>>>(q, v, m, out, attn, write_attn);
}

// round 12
// speedup vs baseline: 1.0154x; 1.0154x over previous
#include <cuda_runtime.h>
#include <cstdint>
#include <cstddef>

#define B_      64
#define LQ      1024
#define LK      1024
#define DH      64
#define QT      16
#define CHUNK   128
#define NCH     (LK / CHUNK)   // 8
#define NTHR    512
#define KP32    36             // K smem pitch in u32: bank=(36r+u)%32=(4r+u)%32 -> conflict-free
#define SCP     1028           // sc pitch: score STS conflict-free
#define CAPS    512            // sparsemax compact-list capacity (floats, per warp)
#define CAPG    256            // gather pair capacity (pairs, per warp)
#define TEMP_INV 0.125f
#define REMOVED  (-1.0e30f)
#define CUTV     (-1.0e29f)

// smem: khi[128*36 u32] kmid[128*36 u32] (=9216 floats; reused as 16x576 warp scratch) | sc[16*1028]
#define KS_FLOATS   (2 * CHUNK * KP32)     // 9216
#define SC_FLOATS   (QT * SCP)             // 16448
#define SMEM_FLOATS (KS_FLOATS + SC_FLOATS)
#define SMEM_BYTES  (SMEM_FLOATS * 4)
#define WSCR        576                    // per-warp scratch floats (16*576 = 9216)
#define KMID_BYTE_OFF (CHUNK * KP32 * 4)   // byte offset of kmid_s from khi_s

// pack two fp32 -> f16x2 (lo = x, hi = y)
__device__ __forceinline__ unsigned pack_h2(float x, float y) {
    unsigned r;
    asm("cvt.rn.f16x2.f32 %0, %1, %2;" : "=r"(r) : "f"(y), "f"(x));
    return r;
}
// unpack f16x2 -> two fp32
__device__ __forceinline__ void unpack_h2(unsigned p, float& x, float& y) {
    asm("{ .reg .f16 l, h; mov.b32 {l, h}, %2; cvt.f32.f16 %0, l; cvt.f32.f16 %1, h; }"
        : "=f"(x), "=f"(y) : "r"(p));
}

__device__ __forceinline__ void mma_f16(float& d0, float& d1, float& d2, float& d3,
                                        unsigned a0, unsigned a1, unsigned a2, unsigned a3,
                                        unsigned b0, unsigned b1) {
    asm("mma.sync.aligned.m16n8k16.row.col.f32.f16.f16.f32 "
        "{%0,%1,%2,%3}, {%4,%5,%6,%7}, {%8,%9}, {%0,%1,%2,%3};"
        : "+f"(d0), "+f"(d1), "+f"(d2), "+f"(d3)
        : "r"(a0), "r"(a1), "r"(a2), "r"(a3), "r"(b0), "r"(b1));
}

__device__ __forceinline__ void ldsm_x4(unsigned& r0, unsigned& r1, unsigned& r2, unsigned& r3,
                                        unsigned saddr) {
    asm volatile("ldmatrix.sync.aligned.m8n8.x4.shared.b16 {%0,%1,%2,%3}, [%4];"
                 : "=r"(r0), "=r"(r1), "=r"(r2), "=r"(r3) : "r"(saddr));
}

// --------------------------------------------------------------------------
// SINGLE kernel. One CTA = 16 q-rows of one batch, 512 threads / 16 warps.
// Mask-dtype detection inlined (warp 0, 512 shared bytes, L2-broadcast);
// QK^T: fp16x2 3-term compensated MMA, K split hi/mid during staging,
// A-fragments via ldmatrix.x4. Sparsemax: Michelot + survivor compaction.
// Gather: ballot-compacted (p,j) pairs, 4-way MLP batched V loads.
// --------------------------------------------------------------------------
extern "C" __global__ void __launch_bounds__(NTHR, 2)
sparse_attn_kernel(const float* __restrict__ q,
                   const float* __restrict__ k,
                   const float* __restrict__ v,
                   const void*  __restrict__ maskp,
                   float* __restrict__ out,
                   float* __restrict__ attn,
                   int write_attn)
{
    extern __shared__ float sm[];
    __shared__ int mk_s;                           // mask-dtype kind
    unsigned* khi_s = (unsigned*)sm;               // [CHUNK][KP32] f16x2 (hi)
    float*    sc    = sm + KS_FLOATS;              // [QT][SCP]

    const int tid  = threadIdx.x;
    const int w    = tid >> 5;
    const int lane = tid & 31;
    const int b    = blockIdx.y;
    const int q0   = blockIdx.x * QT;

    // ---- inline mask-dtype detection (warp 0; hidden behind GEMM) ----
    // bytes are only 0/1-valued:  int32 -> nonzero only at offset%4==0;
    // float32 (1.0f=00 00 80 3F) -> nonzero only at offsets 2,3; uint8 -> all.
    if (w == 0) {
        uint4 u = ((const uint4*)maskp)[lane];     // shared 512 bytes, L2-broadcast
        unsigned fl = 0;
        #pragma unroll
        for (int bt = 0; bt < 4; ++bt) {
            unsigned uu = (&u.x)[bt];
            if (uu & 0x000000FFu) fl |= 1u;
            if (uu & 0x0000FF00u) fl |= 2u;
            if (uu & 0x00FF0000u) fl |= 4u;
            if (uu & 0xFF000000u) fl |= 8u;
        }
        fl = __reduce_or_sync(0xFFFFFFFFu, fl);
        if (lane == 0) {
            int kind;
            if ((fl & 0xEu) == 0)               kind = 1;  // int32
            else if ((fl & 1u) == 0 && (fl & 8u)) kind = 2; // float32
            else                                 kind = 0;  // uint8 / bool
            mk_s = kind;
        }
    }

    // ---- Q subtile (w>>3) as f16x2 B fragments (hi + mid), 16 regs ----
    unsigned bh0[4], bh1[4], bm0[4], bm1[4];
    {
        const float* qb = q + ((size_t)(b * LQ + q0 + 8 * (w >> 3) + (lane >> 2))) * DH + 2 * (lane & 3);
        #pragma unroll
        for (int ks = 0; ks < 4; ++ks) {
            float2 p0 = *(const float2*)(qb + ks * 16);
            float2 p1 = *(const float2*)(qb + ks * 16 + 8);
            float f0 = p0.x * TEMP_INV, f1 = p0.y * TEMP_INV;
            float f2 = p1.x * TEMP_INV, f3 = p1.y * TEMP_INV;
            bh0[ks] = pack_h2(f0, f1);
            bh1[ks] = pack_h2(f2, f3);
            float h0, h1, h2, h3;
            unpack_h2(bh0[ks], h0, h1);
            unpack_h2(bh1[ks], h2, h3);
            bm0[ks] = pack_h2(f0 - h0, f1 - h1);
            bm1[ks] = pack_h2(f2 - h2, f3 - h3);
        }
    }
    const int kr0 = 16 * (w & 7);

    // ldmatrix per-lane address (shared space), ks advances by 32 bytes
    unsigned lm_base;
    {
        int g  = lane >> 3;                        // matrix index 0..3
        int rl = lane & 7;
        int row = kr0 + rl + 8 * (g & 1);          // m1/m3 -> rows +8
        unsigned sbase = (unsigned)__cvta_generic_to_shared(khi_s);
        lm_base = sbase + (unsigned)(row * KP32 * 4 + (g >> 1) * 16);   // m2/m3 -> k+8
    }

    // ---- QK^T over 8 chunks of 128 K-rows ----
    for (int c = 0; c < NCH; ++c) {
        __syncthreads();
        // stage K chunk with fp16 hi/mid split (computed once per chunk per CTA)
        #pragma unroll
        for (int it = 0; it < (CHUNK * 16) / NTHR; ++it) {
            int fi = tid + NTHR * it;
            int r  = fi >> 4;
            int d4 = fi & 15;
            const float4 kv = *(const float4*)(k + ((size_t)(b * LK + c * CHUNK + r)) * DH + 4 * d4);
            unsigned hA = pack_h2(kv.x, kv.y);
            unsigned hB = pack_h2(kv.z, kv.w);
            float hx, hy, hz, hw;
            unpack_h2(hA, hx, hy);
            unpack_h2(hB, hz, hw);
            unsigned mA = pack_h2(kv.x - hx, kv.y - hy);
            unsigned mB = pack_h2(kv.z - hz, kv.w - hw);
            int u = r * KP32 + 2 * d4;
            khi_s[u]     = hA;  khi_s[u + 1] = hB;
            khi_s[CHUNK * KP32 + u]     = mA;
            khi_s[CHUNK * KP32 + u + 1] = mB;
        }
        __syncthreads();

        float d0 = 0.f, d1 = 0.f, d2 = 0.f, d3 = 0.f;
        #pragma unroll
        for (int ks = 0; ks < 4; ++ks) {
            unsigned ah0, ah1, ah2, ah3, am0, am1, am2, am3;
            ldsm_x4(ah0, ah1, ah2, ah3, lm_base + ks * 32);
            ldsm_x4(am0, am1, am2, am3, lm_base + KMID_BYTE_OFF + ks * 32);
            mma_f16(d0, d1, d2, d3, ah0, ah1, ah2, ah3, bm0[ks], bm1[ks]);  // hi*mid
            mma_f16(d0, d1, d2, d3, am0, am1, am2, am3, bh0[ks], bh1[ks]);  // mid*hi
            mma_f16(d0, d1, d2, d3, ah0, ah1, ah2, ah3, bh0[ks], bh1[ks]);  // hi*hi
        }
        // C 16x8: rows = k, cols = q
        int kg = c * CHUNK + kr0 + (lane >> 2);
        int qc = 8 * (w >> 3) + 2 * (lane & 3);
        sc[qc * SCP + kg]           = d0;
        sc[(qc + 1) * SCP + kg]     = d1;
        sc[qc * SCP + kg + 8]       = d2;
        sc[(qc + 1) * SCP + kg + 8] = d3;
    }
    __syncthreads();

    // ---- mask pass, 16-byte vectorized ----
    {
        const int mkind = mk_s;
        size_t mbase = ((size_t)b * LQ + q0) * LK;
        if (mkind == 0) {
            const uint4* m4 = (const uint4*)((const unsigned char*)maskp + mbase);
            #pragma unroll
            for (int it = 0; it < (QT * LK) / 16 / NTHR; ++it) {
                int idx  = tid + NTHR * it;
                uint4 u  = m4[idx];
                int base = idx * 16;
                float* srow = sc + (base >> 10) * SCP + (base & 1023);
                #pragma unroll
                for (int bt = 0; bt < 4; ++bt) {
                    unsigned uu = (&u.x)[bt];
                    if (uu & 0x000000FFu) srow[bt * 4 + 0] = REMOVED;
                    if (uu & 0x0000FF00u) srow[bt * 4 + 1] = REMOVED;
                    if (uu & 0x00FF0000u) srow[bt * 4 + 2] = REMOVED;
                    if (uu & 0xFF000000u) srow[bt * 4 + 3] = REMOVED;
                }
            }
        } else {
            const uint4* m4 = (const uint4*)((const unsigned*)maskp + mbase);
            #pragma unroll
            for (int it = 0; it < (QT * LK) / 4 / NTHR; ++it) {
                int idx  = tid + NTHR * it;
                uint4 u  = m4[idx];
                int base = idx * 4;
                float* srow = sc + (base >> 10) * SCP + (base & 1023);
                if (u.x) srow[0] = REMOVED;
                if (u.y) srow[1] = REMOVED;
                if (u.z) srow[2] = REMOVED;
                if (u.w) srow[3] = REMOVED;
            }
        }
    }
    __syncthreads();   // also fences k_s scratch reuse (GEMM reads done)

    // ---- sparsemax (warp w owns row w): Michelot with survivor compaction ----
    const float* zr = sc + w * SCP;
    float* wsc = sm + w * WSCR;            // per-warp scratch in dead K region
    const unsigned lt = (1u << lane) - 1u;

    float S = 0.0f; int Cl = 0;
    #pragma unroll
    for (int t4 = 0; t4 < 8; ++t4) {
        float4 zv = *(const float4*)(zr + 4 * lane + 128 * t4);
        if (zv.x > CUTV) { S += zv.x; Cl++; }
        if (zv.y > CUTV) { S += zv.y; Cl++; }
        if (zv.z > CUTV) { S += zv.z; Cl++; }
        if (zv.w > CUTV) { S += zv.w; Cl++; }
    }
    #pragma unroll
    for (int o = 16; o; o >>= 1) S += __shfl_xor_sync(0xFFFFFFFFu, S, o);
    int C = __reduce_add_sync(0xFFFFFFFFu, Cl);

    float tau;
    if (C > 0) {
        tau = (S - 1.0f) / (float)C;
        // compacting scan with tau0: survivors -> wsc (support set shrinks monotonically)
        float s2 = 0.0f; int c2l = 0; int cnt = 0;
        #pragma unroll
        for (int t4 = 0; t4 < 8; ++t4) {
            float4 zv = *(const float4*)(zr + 4 * lane + 128 * t4);
            #pragma unroll
            for (int e = 0; e < 4; ++e) {
                float ze = (&zv.x)[e];
                bool a = ze > tau;
                unsigned bb = __ballot_sync(0xFFFFFFFFu, a);
                if (a) {
                    int ps = cnt + __popc(bb & lt);
                    if (ps < CAPS) wsc[ps] = ze;
                    s2 += ze; c2l++;
                }
                cnt += __popc(bb);
            }
        }
        int c2 = __reduce_add_sync(0xFFFFFFFFu, c2l);
        #pragma unroll
        for (int o = 16; o; o >>= 1) s2 += __shfl_xor_sync(0xFFFFFFFFu, s2, o);

        if (c2 != C) {
            if (cnt <= CAPS) {
                __syncwarp();
                S = s2; C = c2;
                tau = (S - 1.0f) / (float)C;
                for (int iter = 0; iter < 64; ++iter) {
                    float s3 = 0.0f; int c3l = 0;
                    for (int i = lane; i < cnt; i += 32) {
                        float z3 = wsc[i];
                        if (z3 > tau) { s3 += z3; c3l++; }
                    }
                    int c3 = __reduce_add_sync(0xFFFFFFFFu, c3l);
                    #pragma unroll
                    for (int o = 16; o; o >>= 1) s3 += __shfl_xor_sync(0xFFFFFFFFu, s3, o);
                    if (c3 == C) break;
                    S = s3; C = c3;
                    tau = (S - 1.0f) / (float)C;
                }
            } else {
                // stateless fallback (huge support)
                S = s2; C = c2;
                tau = (S - 1.0f) / (float)C;
                for (int iter = 0; iter < 64; ++iter) {
                    float s3 = 0.0f; int c3l = 0;
                    #pragma unroll
                    for (int t4 = 0; t4 < 8; ++t4) {
                        float4 zv = *(const float4*)(zr + 4 * lane + 128 * t4);
                        if (zv.x > tau) { s3 += zv.x; c3l++; }
                        if (zv.y > tau) { s3 += zv.y; c3l++; }
                        if (zv.z > tau) { s3 += zv.z; c3l++; }
                        if (zv.w > tau) { s3 += zv.w; c3l++; }
                    }
                    int c3 = __reduce_add_sync(0xFFFFFFFFu, c3l);
                    #pragma unroll
                    for (int o = 16; o; o >>= 1) s3 += __shfl_xor_sync(0xFFFFFFFFu, s3, o);
                    if (c3 == C) break;
                    S = s3; C = c3;
                    tau = (S - 1.0f) / (float)C;
                }
            }
        }
    } else {
        tau = 1.0e30f;                     // fully-masked row
    }
    __syncwarp();

    // ---- probabilities -> attn (float4 stores) + ballot-compacted (p,j) pairs ----
    const float2* vb2 = (const float2*)(v + (size_t)b * LK * DH);
    float* cp = wsc;                       // reuse scratch for (p, j) pairs
    float* arow = attn + ((size_t)(b * LQ + q0 + w)) * LK;
    float2 acc2 = make_float2(0.0f, 0.0f);
    int cnt = 0;

    #pragma unroll
    for (int tt = 0; tt < 8; ++tt) {
        const int j0 = 4 * lane + 128 * tt;
        float4 zv = *(const float4*)(zr + j0);
        float4 pv;
        pv.x = fmaxf(zv.x - tau, 0.0f);
        pv.y = fmaxf(zv.y - tau, 0.0f);
        pv.z = fmaxf(zv.z - tau, 0.0f);
        pv.w = fmaxf(zv.w - tau, 0.0f);
        if (write_attn) *(float4*)(arow + j0) = pv;

        unsigned bb0 = __ballot_sync(0xFFFFFFFFu, pv.x > 0.0f);
        unsigned bb1 = __ballot_sync(0xFFFFFFFFu, pv.y > 0.0f);
        unsigned bb2 = __ballot_sync(0xFFFFFFFFu, pv.z > 0.0f);
        unsigned bb3 = __ballot_sync(0xFFFFFFFFu, pv.w > 0.0f);
        int base0 = cnt;
        int base1 = base0 + __popc(bb0);
        int base2 = base1 + __popc(bb1);
        int base3 = base2 + __popc(bb2);
        cnt       = base3 + __popc(bb3);

        int ps;
        ps = base0 + __popc(bb0 & lt);
        if (pv.x > 0.0f && ps < CAPG) { cp[2 * ps] = pv.x; cp[2 * ps + 1] = __int_as_float(j0); }
        ps = base1 + __popc(bb1 & lt);
        if (pv.y > 0.0f && ps < CAPG) { cp[2 * ps] = pv.y; cp[2 * ps + 1] = __int_as_float(j0 + 1); }
        ps = base2 + __popc(bb2 & lt);
        if (pv.z > 0.0f && ps < CAPG) { cp[2 * ps] = pv.z; cp[2 * ps + 1] = __int_as_float(j0 + 2); }
        ps = base3 + __popc(bb3 & lt);
        if (pv.w > 0.0f && ps < CAPG) { cp[2 * ps] = pv.w; cp[2 * ps + 1] = __int_as_float(j0 + 3); }

        // overflow (support > CAPG): serial fallback for spilled entries
        if (cnt > CAPG) {
            #pragma unroll
            for (int e = 0; e < 4; ++e) {
                float pe = (&pv.x)[e];
                unsigned bb = (e == 0) ? bb0 : (e == 1) ? bb1 : (e == 2) ? bb2 : bb3;
                int be     = (e == 0) ? base0 : (e == 1) ? base1 : (e == 2) ? base2 : base3;
                unsigned ovf = __ballot_sync(0xFFFFFFFFu,
                                             pe > 0.0f && (be + __popc(bb & lt)) >= CAPG);
                while (ovf) {
                    int src = __ffs(ovf) - 1;
                    ovf &= ovf - 1;
                    float pj = __shfl_sync(0xFFFFFFFFu, pe, src);
                    int j = 4 * src + 128 * tt + e;
                    const float2 vv = vb2[j * 32 + lane];
                    acc2.x += pj * vv.x;
                    acc2.y += pj * vv.y;
                }
            }
        }
    }
    __syncwarp();

    // ---- batched V gather: 4 independent loads in flight ----
    {
        const int cn = cnt < CAPG ? cnt : CAPG;
        int i = 0;
        for (; i + 4 <= cn; i += 4) {
            float4 e0 = *(const float4*)(cp + 2 * i);
            float4 e1 = *(const float4*)(cp + 2 * i + 4);
            const float2 v0 = vb2[__float_as_int(e0.y) * 32 + lane];
            const float2 v1 = vb2[__float_as_int(e0.w) * 32 + lane];
            const float2 v2 = vb2[__float_as_int(e1.y) * 32 + lane];
            const float2 v3 = vb2[__float_as_int(e1.w) * 32 + lane];
            acc2.x += e0.x * v0.x;  acc2.y += e0.x * v0.y;
            acc2.x += e0.z * v1.x;  acc2.y += e0.z * v1.y;
            acc2.x += e1.x * v2.x;  acc2.y += e1.x * v2.y;
            acc2.x += e1.z * v3.x;  acc2.y += e1.z * v3.y;
        }
        for (; i < cn; ++i) {
            float p = cp[2 * i];
            int  j  = __float_as_int(cp[2 * i + 1]);
            const float2 vv = vb2[j * 32 + lane];
            acc2.x += p * vv.x;
            acc2.y += p * vv.y;
        }
    }

    *(float2*)(out + ((size_t)(b * LQ + q0 + w)) * DH + 2 * lane) = acc2;
}

// --------------------------------------------------------------------------
extern "C" void kernel_launch(void* const* d_in, const int* in_sizes, int n_in,
                              void* d_out, int out_size) {
    const float* q = (const float*)d_in[0];
    const float* k = (const float*)d_in[1];
    const float* v = (const float*)d_in[2];
    const void*  m = d_in[3];

    float* out = (float*)d_out;
    long long out_elems  = (long long)B_ * LQ * DH;
    long long attn_elems = (long long)B_ * LQ * LK;
    int write_attn = ((long long)out_size >= out_elems + attn_elems) ? 1 : 0;
    float* attn = out + (size_t)out_elems;

    cudaFuncSetAttribute(sparse_attn_kernel,
                         cudaFuncAttributeMaxDynamicSharedMemorySize, SMEM_BYTES);

    dim3 grid(LQ / QT, B_);
    sparse_attn_kernel<<<grid, NTHR, SMEM_BYTES>>>(q, k, v, m, out, attn, write_attn);
}

// round 13
// speedup vs baseline: 1.0832x; 1.0668x over previous
#include <cuda_runtime.h>
#include <cstdint>
#include <cstddef>

#define B_      64
#define LQ      1024
#define LK      1024
#define DH      64
#define QT      16
#define CHUNK   128
#define NCH     (LK / CHUNK)   // 8
#define NU      (2 * NCH)      // 16 pipeline units (hi/mid per chunk)
#define NTHR    512
#define KP32    36             // K smem pitch in u32: bank=(4r+u)%32 -> conflict-free
#define SCP     1028           // sc pitch: score STS conflict-free
#define CAPS    512            // sparsemax compact-list capacity (floats, per warp)
#define CAPG    256            // gather pair capacity (pairs, per warp)
#define TEMP_INV 0.125f
#define REMOVED  (-1.0e30f)
#define CUTV     (-1.0e29f)

// smem: slot0 hi[128*36 u32] | slot1 mid[128*36 u32] (=9216 floats; reused as 16x576 scratch) | sc[16*1028]
#define KS_FLOATS   (2 * CHUNK * KP32)     // 9216
#define SC_FLOATS   (QT * SCP)             // 16448
#define SMEM_FLOATS (KS_FLOATS + SC_FLOATS)
#define SMEM_BYTES  (SMEM_FLOATS * 4)
#define WSCR        576                    // per-warp scratch floats (16*576 = 9216)
#define KMID_BYTE_OFF (CHUNK * KP32 * 4)   // byte offset of slot1 from slot0

#define KELEMS  (B_ * LK * DH)             // 4,194,304
#define KU32S   (KELEMS / 2)               // f16x2 words per split array

__device__ int      g_mask_kind;           // 0 = uint8/bool, 1 = int32, 2 = float32
__device__ unsigned g_khi[KU32S];          // K fp16 hi  (f16x2-packed), built per launch
__device__ unsigned g_kmid[KU32S];         // K fp16 mid residual

// pack two fp32 -> f16x2 (lo = x, hi = y)
__device__ __forceinline__ unsigned pack_h2(float x, float y) {
    unsigned r;
    asm("cvt.rn.f16x2.f32 %0, %1, %2;" : "=r"(r) : "f"(y), "f"(x));
    return r;
}
// unpack f16x2 -> two fp32
__device__ __forceinline__ void unpack_h2(unsigned p, float& x, float& y) {
    asm("{ .reg .f16 l, h; mov.b32 {l, h}, %2; cvt.f32.f16 %0, l; cvt.f32.f16 %1, h; }"
        : "=f"(x), "=f"(y) : "r"(p));
}

// ---- prep: K fp16 hi/mid split (byte-neutral) + mask-dtype detection ----
__global__ void prep_kernel(const float* __restrict__ k, const unsigned char* __restrict__ m) {
    if (blockIdx.x == 0 && threadIdx.x < 32) {
        uint4 u = ((const uint4*)m)[threadIdx.x];   // 512 bytes sample
        unsigned fl = 0;
        #pragma unroll
        for (int bt = 0; bt < 4; ++bt) {
            unsigned uu = (&u.x)[bt];
            if (uu & 0x000000FFu) fl |= 1u;
            if (uu & 0x0000FF00u) fl |= 2u;
            if (uu & 0x00FF0000u) fl |= 4u;
            if (uu & 0xFF000000u) fl |= 8u;
        }
        fl = __reduce_or_sync(0xFFFFFFFFu, fl);
        if (threadIdx.x == 0) {
            int kind;
            if ((fl & 0xEu) == 0)                 kind = 1;  // int32
            else if ((fl & 1u) == 0 && (fl & 8u)) kind = 2;  // float32
            else                                  kind = 0;  // uint8 / bool
            g_mask_kind = kind;
        }
    }
    int i = blockIdx.x * 256 + threadIdx.x;        // float4 index
    float4 kv = ((const float4*)k)[i];
    unsigned hA = pack_h2(kv.x, kv.y);
    unsigned hB = pack_h2(kv.z, kv.w);
    float hx, hy, hz, hw;
    unpack_h2(hA, hx, hy);
    unpack_h2(hB, hz, hw);
    unsigned mA = pack_h2(kv.x - hx, kv.y - hy);
    unsigned mB = pack_h2(kv.z - hz, kv.w - hw);
    ((uint2*)g_khi)[i]  = make_uint2(hA, hB);
    ((uint2*)g_kmid)[i] = make_uint2(mA, mB);
}

__device__ __forceinline__ void mma_f16(float& d0, float& d1, float& d2, float& d3,
                                        unsigned a0, unsigned a1, unsigned a2, unsigned a3,
                                        unsigned b0, unsigned b1) {
    asm("mma.sync.aligned.m16n8k16.row.col.f32.f16.f16.f32 "
        "{%0,%1,%2,%3}, {%4,%5,%6,%7}, {%8,%9}, {%0,%1,%2,%3};"
        : "+f"(d0), "+f"(d1), "+f"(d2), "+f"(d3)
        : "r"(a0), "r"(a1), "r"(a2), "r"(a3), "r"(b0), "r"(b1));
}

__device__ __forceinline__ void ldsm_x4(unsigned& r0, unsigned& r1, unsigned& r2, unsigned& r3,
                                        unsigned saddr) {
    asm volatile("ldmatrix.sync.aligned.m8n8.x4.shared.b16 {%0,%1,%2,%3}, [%4];"
                 : "=r"(r0), "=r"(r1), "=r"(r2), "=r"(r3) : "r"(saddr));
}

__device__ __forceinline__ void cp_async16(unsigned dst, const void* src) {
    asm volatile("cp.async.cg.shared.global [%0], [%1], 16;" :: "r"(dst), "l"(src) : "memory");
}

// --------------------------------------------------------------------------
// One CTA = 16 q-rows of one batch, 512 threads / 16 warps.
// QK^T: fp16x2 3-term compensated MMA over a cp.async lookahead-1 pipeline:
// unit 2c = K-hi(c) -> slot0 (hi*mid + hi*hi), unit 2c+1 = K-mid(c) -> slot1
// (mid*hi + score STS). Each unit's copy is issued one compute phase ahead.
// Sparsemax: Michelot + survivor compaction. Gather: ballot-compacted (p,j)
// pairs, 4-way MLP batched V loads.
// --------------------------------------------------------------------------
extern "C" __global__ void __launch_bounds__(NTHR, 2)
sparse_attn_kernel(const float* __restrict__ q,
                   const float* __restrict__ v,
                   const void*  __restrict__ maskp,
                   float* __restrict__ out,
                   float* __restrict__ attn,
                   int write_attn)
{
    extern __shared__ float sm[];
    unsigned* khi_s = (unsigned*)sm;               // slot0; slot1 at +KMID_BYTE_OFF
    float*    sc    = sm + KS_FLOATS;              // [QT][SCP]

    const int tid  = threadIdx.x;
    const int w    = tid >> 5;
    const int lane = tid & 31;
    const int b    = blockIdx.y;
    const int q0   = blockIdx.x * QT;
    const int mkind = g_mask_kind;

    // ---- Q subtile (w>>3) as f16x2 B fragments (hi + mid), 16 regs ----
    unsigned bh0[4], bh1[4], bm0[4], bm1[4];
    {
        const float* qb = q + ((size_t)(b * LQ + q0 + 8 * (w >> 3) + (lane >> 2))) * DH + 2 * (lane & 3);
        #pragma unroll
        for (int ks = 0; ks < 4; ++ks) {
            float2 p0 = *(const float2*)(qb + ks * 16);
            float2 p1 = *(const float2*)(qb + ks * 16 + 8);
            float f0 = p0.x * TEMP_INV, f1 = p0.y * TEMP_INV;
            float f2 = p1.x * TEMP_INV, f3 = p1.y * TEMP_INV;
            bh0[ks] = pack_h2(f0, f1);
            bh1[ks] = pack_h2(f2, f3);
            float h0, h1, h2, h3;
            unpack_h2(bh0[ks], h0, h1);
            unpack_h2(bh1[ks], h2, h3);
            bm0[ks] = pack_h2(f0 - h0, f1 - h1);
            bm1[ks] = pack_h2(f2 - h2, f3 - h3);
        }
    }
    const int kr0 = 16 * (w & 7);

    const unsigned sm_shared = (unsigned)__cvta_generic_to_shared(khi_s);

    // ldmatrix per-lane address (shared space), ks advances by 32 bytes
    unsigned lm_base;
    {
        int g  = lane >> 3;                        // matrix index 0..3
        int rl = lane & 7;
        int row = kr0 + rl + 8 * (g & 1);          // m1/m3 -> rows +8
        lm_base = sm_shared + (unsigned)(row * KP32 * 4 + (g >> 1) * 16);   // m2/m3 -> k+8
    }

    // per-thread staging addresses (2 x 16B per unit)
    const int fi0 = tid, fi1 = tid + NTHR;
    const unsigned sd0 = (unsigned)(((fi0 >> 3) * KP32 + 4 * (fi0 & 7)) * 4);
    const unsigned sd1 = (unsigned)(((fi1 >> 3) * KP32 + 4 * (fi1 & 7)) * 4);

    // ---- QK^T pipeline over 16 units ----
    {
        // prologue: issue unit 0 (hi of chunk 0)
        {
            const unsigned* gsrc = g_khi + (size_t)(b * LK) * (DH / 2);
            cp_async16(sm_shared + sd0, gsrc + fi0 * 4);
            cp_async16(sm_shared + sd1, gsrc + fi1 * 4);
            asm volatile("cp.async.commit_group;" ::: "memory");
        }

        float d0 = 0.f, d1 = 0.f, d2 = 0.f, d3 = 0.f;
        for (int u = 0; u < NU; ++u) {
            asm volatile("cp.async.wait_group 0;" ::: "memory");
            __syncthreads();                        // unit u visible; prev unit's readers done
            if (u + 1 < NU) {
                int cn = (u + 1) >> 1;
                const unsigned* gsrc = (((u + 1) & 1) ? g_kmid : g_khi)
                                       + (size_t)(b * LK + cn * CHUNK) * (DH / 2);
                unsigned dstb = sm_shared + ((u + 1) & 1) * KMID_BYTE_OFF;
                cp_async16(dstb + sd0, gsrc + fi0 * 4);
                cp_async16(dstb + sd1, gsrc + fi1 * 4);
                asm volatile("cp.async.commit_group;" ::: "memory");
            }
            if (!(u & 1)) {
                // hi unit: hi*mid + hi*hi
                d0 = d1 = d2 = d3 = 0.f;
                #pragma unroll
                for (int ks = 0; ks < 4; ++ks) {
                    unsigned a0, a1, a2, a3;
                    ldsm_x4(a0, a1, a2, a3, lm_base + ks * 32);
                    mma_f16(d0, d1, d2, d3, a0, a1, a2, a3, bm0[ks], bm1[ks]);
                    mma_f16(d0, d1, d2, d3, a0, a1, a2, a3, bh0[ks], bh1[ks]);
                }
            } else {
                // mid unit: mid*hi, then score epilogue for chunk c
                #pragma unroll
                for (int ks = 0; ks < 4; ++ks) {
                    unsigned a0, a1, a2, a3;
                    ldsm_x4(a0, a1, a2, a3, lm_base + KMID_BYTE_OFF + ks * 32);
                    mma_f16(d0, d1, d2, d3, a0, a1, a2, a3, bh0[ks], bh1[ks]);
                }
                int c  = u >> 1;
                int kg = c * CHUNK + kr0 + (lane >> 2);
                int qc = 8 * (w >> 3) + 2 * (lane & 3);
                sc[qc * SCP + kg]           = d0;
                sc[(qc + 1) * SCP + kg]     = d1;
                sc[qc * SCP + kg + 8]       = d2;
                sc[(qc + 1) * SCP + kg + 8] = d3;
            }
        }
    }
    __syncthreads();

    // ---- mask pass, 16-byte vectorized ----
    {
        size_t mbase = ((size_t)b * LQ + q0) * LK;
        if (mkind == 0) {
            const uint4* m4 = (const uint4*)((const unsigned char*)maskp + mbase);
            #pragma unroll
            for (int it = 0; it < (QT * LK) / 16 / NTHR; ++it) {
                int idx  = tid + NTHR * it;
                uint4 u  = m4[idx];
                int base = idx * 16;
                float* srow = sc + (base >> 10) * SCP + (base & 1023);
                #pragma unroll
                for (int bt = 0; bt < 4; ++bt) {
                    unsigned uu = (&u.x)[bt];
                    if (uu & 0x000000FFu) srow[bt * 4 + 0] = REMOVED;
                    if (uu & 0x0000FF00u) srow[bt * 4 + 1] = REMOVED;
                    if (uu & 0x00FF0000u) srow[bt * 4 + 2] = REMOVED;
                    if (uu & 0xFF000000u) srow[bt * 4 + 3] = REMOVED;
                }
            }
        } else {
            const uint4* m4 = (const uint4*)((const unsigned*)maskp + mbase);
            #pragma unroll
            for (int it = 0; it < (QT * LK) / 4 / NTHR; ++it) {
                int idx  = tid + NTHR * it;
                uint4 u  = m4[idx];
                int base = idx * 4;
                float* srow = sc + (base >> 10) * SCP + (base & 1023);
                if (u.x) srow[0] = REMOVED;
                if (u.y) srow[1] = REMOVED;
                if (u.z) srow[2] = REMOVED;
                if (u.w) srow[3] = REMOVED;
            }
        }
    }
    __syncthreads();   // also fences K-slot scratch reuse (GEMM reads done)

    // ---- sparsemax (warp w owns row w): Michelot with survivor compaction ----
    const float* zr = sc + w * SCP;
    float* wsc = sm + w * WSCR;            // per-warp scratch in dead K region
    const unsigned lt = (1u << lane) - 1u;

    float S = 0.0f; int Cl = 0;
    #pragma unroll
    for (int t4 = 0; t4 < 8; ++t4) {
        float4 zv = *(const float4*)(zr + 4 * lane + 128 * t4);
        if (zv.x > CUTV) { S += zv.x; Cl++; }
        if (zv.y > CUTV) { S += zv.y; Cl++; }
        if (zv.z > CUTV) { S += zv.z; Cl++; }
        if (zv.w > CUTV) { S += zv.w; Cl++; }
    }
    #pragma unroll
    for (int o = 16; o; o >>= 1) S += __shfl_xor_sync(0xFFFFFFFFu, S, o);
    int C = __reduce_add_sync(0xFFFFFFFFu, Cl);

    float tau;
    if (C > 0) {
        tau = (S - 1.0f) / (float)C;
        float s2 = 0.0f; int c2l = 0; int cnt = 0;
        #pragma unroll
        for (int t4 = 0; t4 < 8; ++t4) {
            float4 zv = *(const float4*)(zr + 4 * lane + 128 * t4);
            #pragma unroll
            for (int e = 0; e < 4; ++e) {
                float ze = (&zv.x)[e];
                bool a = ze > tau;
                unsigned bb = __ballot_sync(0xFFFFFFFFu, a);
                if (a) {
                    int ps = cnt + __popc(bb & lt);
                    if (ps < CAPS) wsc[ps] = ze;
                    s2 += ze; c2l++;
                }
                cnt += __popc(bb);
            }
        }
        int c2 = __reduce_add_sync(0xFFFFFFFFu, c2l);
        #pragma unroll
        for (int o = 16; o; o >>= 1) s2 += __shfl_xor_sync(0xFFFFFFFFu, s2, o);

        if (c2 != C) {
            if (cnt <= CAPS) {
                __syncwarp();
                S = s2; C = c2;
                tau = (S - 1.0f) / (float)C;
                for (int iter = 0; iter < 64; ++iter) {
                    float s3 = 0.0f; int c3l = 0;
                    for (int i = lane; i < cnt; i += 32) {
                        float z3 = wsc[i];
                        if (z3 > tau) { s3 += z3; c3l++; }
                    }
                    int c3 = __reduce_add_sync(0xFFFFFFFFu, c3l);
                    #pragma unroll
                    for (int o = 16; o; o >>= 1) s3 += __shfl_xor_sync(0xFFFFFFFFu, s3, o);
                    if (c3 == C) break;
                    S = s3; C = c3;
                    tau = (S - 1.0f) / (float)C;
                }
            } else {
                S = s2; C = c2;
                tau = (S - 1.0f) / (float)C;
                for (int iter = 0; iter < 64; ++iter) {
                    float s3 = 0.0f; int c3l = 0;
                    #pragma unroll
                    for (int t4 = 0; t4 < 8; ++t4) {
                        float4 zv = *(const float4*)(zr + 4 * lane + 128 * t4);
                        if (zv.x > tau) { s3 += zv.x; c3l++; }
                        if (zv.y > tau) { s3 += zv.y; c3l++; }
                        if (zv.z > tau) { s3 += zv.z; c3l++; }
                        if (zv.w > tau) { s3 += zv.w; c3l++; }
                    }
                    int c3 = __reduce_add_sync(0xFFFFFFFFu, c3l);
                    #pragma unroll
                    for (int o = 16; o; o >>= 1) s3 += __shfl_xor_sync(0xFFFFFFFFu, s3, o);
                    if (c3 == C) break;
                    S = s3; C = c3;
                    tau = (S - 1.0f) / (float)C;
                }
            }
        }
    } else {
        tau = 1.0e30f;                     // fully-masked row
    }
    __syncwarp();

    // ---- probabilities -> attn (float4 stores) + ballot-compacted (p,j) pairs ----
    const float2* vb2 = (const float2*)(v + (size_t)b * LK * DH);
    float* cp = wsc;                       // reuse scratch for (p, j) pairs
    float* arow = attn + ((size_t)(b * LQ + q0 + w)) * LK;
    float2 acc2 = make_float2(0.0f, 0.0f);
    int cnt = 0;

    #pragma unroll
    for (int tt = 0; tt < 8; ++tt) {
        const int j0 = 4 * lane + 128 * tt;
        float4 zv = *(const float4*)(zr + j0);
        float4 pv;
        pv.x = fmaxf(zv.x - tau, 0.0f);
        pv.y = fmaxf(zv.y - tau, 0.0f);
        pv.z = fmaxf(zv.z - tau, 0.0f);
        pv.w = fmaxf(zv.w - tau, 0.0f);
        if (write_attn) *(float4*)(arow + j0) = pv;

        unsigned bb0 = __ballot_sync(0xFFFFFFFFu, pv.x > 0.0f);
        unsigned bb1 = __ballot_sync(0xFFFFFFFFu, pv.y > 0.0f);
        unsigned bb2 = __ballot_sync(0xFFFFFFFFu, pv.z > 0.0f);
        unsigned bb3 = __ballot_sync(0xFFFFFFFFu, pv.w > 0.0f);
        int base0 = cnt;
        int base1 = base0 + __popc(bb0);
        int base2 = base1 + __popc(bb1);
        int base3 = base2 + __popc(bb2);
        cnt       = base3 + __popc(bb3);

        int ps;
        ps = base0 + __popc(bb0 & lt);
        if (pv.x > 0.0f && ps < CAPG) { cp[2 * ps] = pv.x; cp[2 * ps + 1] = __int_as_float(j0); }
        ps = base1 + __popc(bb1 & lt);
        if (pv.y > 0.0f && ps < CAPG) { cp[2 * ps] = pv.y; cp[2 * ps + 1] = __int_as_float(j0 + 1); }
        ps = base2 + __popc(bb2 & lt);
        if (pv.z > 0.0f && ps < CAPG) { cp[2 * ps] = pv.z; cp[2 * ps + 1] = __int_as_float(j0 + 2); }
        ps = base3 + __popc(bb3 & lt);
        if (pv.w > 0.0f && ps < CAPG) { cp[2 * ps] = pv.w; cp[2 * ps + 1] = __int_as_float(j0 + 3); }

        if (cnt > CAPG) {
            #pragma unroll
            for (int e = 0; e < 4; ++e) {
                float pe = (&pv.x)[e];
                unsigned bb = (e == 0) ? bb0 : (e == 1) ? bb1 : (e == 2) ? bb2 : bb3;
                int be     = (e == 0) ? base0 : (e == 1) ? base1 : (e == 2) ? base2 : base3;
                unsigned ovf = __ballot_sync(0xFFFFFFFFu,
                                             pe > 0.0f && (be + __popc(bb & lt)) >= CAPG);
                while (ovf) {
                    int src = __ffs(ovf) - 1;
                    ovf &= ovf - 1;
                    float pj = __shfl_sync(0xFFFFFFFFu, pe, src);
                    int j = 4 * src + 128 * tt + e;
                    const float2 vv = vb2[j * 32 + lane];
                    acc2.x += pj * vv.x;
                    acc2.y += pj * vv.y;
                }
            }
        }
    }
    __syncwarp();

    // ---- batched V gather: 4 independent loads in flight ----
    {
        const int cn = cnt < CAPG ? cnt : CAPG;
        int i = 0;
        for (; i + 4 <= cn; i += 4) {
            float4 e0 = *(const float4*)(cp + 2 * i);
            float4 e1 = *(const float4*)(cp + 2 * i + 4);
            const float2 v0 = vb2[__float_as_int(e0.y) * 32 + lane];
            const float2 v1 = vb2[__float_as_int(e0.w) * 32 + lane];
            const float2 v2 = vb2[__float_as_int(e1.y) * 32 + lane];
            const float2 v3 = vb2[__float_as_int(e1.w) * 32 + lane];
            acc2.x += e0.x * v0.x;  acc2.y += e0.x * v0.y;
            acc2.x += e0.z * v1.x;  acc2.y += e0.z * v1.y;
            acc2.x += e1.x * v2.x;  acc2.y += e1.x * v2.y;
            acc2.x += e1.z * v3.x;  acc2.y += e1.z * v3.y;
        }
        for (; i < cn; ++i) {
            float p = cp[2 * i];
            int  j  = __float_as_int(cp[2 * i + 1]);
            const float2 vv = vb2[j * 32 + lane];
            acc2.x += p * vv.x;
            acc2.y += p * vv.y;
        }
    }

    *(float2*)(out + ((size_t)(b * LQ + q0 + w)) * DH + 2 * lane) = acc2;
}

// --------------------------------------------------------------------------
extern "C" void kernel_launch(void* const* d_in, const int* in_sizes, int n_in,
                              void* d_out, int out_size) {
    const float* q = (const float*)d_in[0];
    const float* k = (const float*)d_in[1];
    const float* v = (const float*)d_in[2];
    const void*  m = d_in[3];

    float* out = (float*)d_out;
    long long out_elems  = (long long)B_ * LQ * DH;
    long long attn_elems = (long long)B_ * LQ * LK;
    int write_attn = ((long long)out_size >= out_elems + attn_elems) ? 1 : 0;
    float* attn = out + (size_t)out_elems;

    prep_kernel<<<KELEMS / 4 / 256, 256>>>(k, (const unsigned char*)m);

    cudaFuncSetAttribute(sparse_attn_kernel,
                         cudaFuncAttributeMaxDynamicSharedMemorySize, SMEM_BYTES);

    dim3 grid(LQ / QT, B_);
    sparse_attn_kernel<<<grid, NTHR, SMEM_BYTES>>>(q, v, m, out, attn, write_attn);
}

// round 14
// speedup vs baseline: 1.1700x; 1.0801x over previous
#include <cuda_runtime.h>
#include <cstdint>
#include <cstddef>

#define B_      64
#define LQ      1024
#define LK      1024
#define DH      64
#define QT      16
#define CHUNK   128
#define NCH     (LK / CHUNK)   // 8
#define NU      (2 * NCH)      // 16 pipeline units (hi/mid per chunk)
#define NTHR    512
#define KP32    36             // K smem pitch in u32: bank=(4r+u)%32 -> conflict-free
#define SCP     1028           // sc pitch: score STS conflict-free
#define CAPS    512            // sparsemax compact-list capacity (floats, per warp)
#define CAPG    256            // gather pair capacity (pairs, per warp)
#define TEMP_INV 0.125f
#define REMOVED  (-1.0e30f)
#define CUTV     (-1.0e29f)

// smem: slot0 hi[128*36 u32] | slot1 mid[128*36 u32] (=9216 floats; reused as 16x576 scratch) | sc[16*1028]
#define KS_FLOATS   (2 * CHUNK * KP32)     // 9216
#define SC_FLOATS   (QT * SCP)             // 16448
#define SMEM_FLOATS (KS_FLOATS + SC_FLOATS)
#define SMEM_BYTES  (SMEM_FLOATS * 4)
#define WSCR        576                    // per-warp scratch floats (16*576 = 9216)
#define KMID_BYTE_OFF (CHUNK * KP32 * 4)   // byte offset of slot1 from slot0

#define KELEMS  (B_ * LK * DH)             // 4,194,304
#define KU32S   (KELEMS / 2)               // f16x2 words per split array

__device__ int      g_mask_kind;           // 0 = uint8/bool, 1 = int32, 2 = float32
__device__ unsigned g_khi[KU32S];          // K fp16 hi  (f16x2-packed), built per launch
__device__ unsigned g_kmid[KU32S];         // K fp16 mid residual

// pack two fp32 -> f16x2 (lo = x, hi = y)
__device__ __forceinline__ unsigned pack_h2(float x, float y) {
    unsigned r;
    asm("cvt.rn.f16x2.f32 %0, %1, %2;" : "=r"(r) : "f"(y), "f"(x));
    return r;
}
// unpack f16x2 -> two fp32
__device__ __forceinline__ void unpack_h2(unsigned p, float& x, float& y) {
    asm("{ .reg .f16 l, h; mov.b32 {l, h}, %2; cvt.f32.f16 %0, l; cvt.f32.f16 %1, h; }"
        : "=f"(x), "=f"(y) : "r"(p));
}

// ---- prep: K fp16 hi/mid split (byte-neutral) + mask-dtype detection ----
__global__ void prep_kernel(const float* __restrict__ k, const unsigned char* __restrict__ m) {
    if (blockIdx.x == 0 && threadIdx.x < 32) {
        uint4 u = ((const uint4*)m)[threadIdx.x];   // 512 bytes sample
        unsigned fl = 0;
        #pragma unroll
        for (int bt = 0; bt < 4; ++bt) {
            unsigned uu = (&u.x)[bt];
            if (uu & 0x000000FFu) fl |= 1u;
            if (uu & 0x0000FF00u) fl |= 2u;
            if (uu & 0x00FF0000u) fl |= 4u;
            if (uu & 0xFF000000u) fl |= 8u;
        }
        fl = __reduce_or_sync(0xFFFFFFFFu, fl);
        if (threadIdx.x == 0) {
            int kind;
            if ((fl & 0xEu) == 0)                 kind = 1;  // int32
            else if ((fl & 1u) == 0 && (fl & 8u)) kind = 2;  // float32
            else                                  kind = 0;  // uint8 / bool
            g_mask_kind = kind;
        }
    }
    int i = blockIdx.x * 256 + threadIdx.x;        // float4 index
    float4 kv = ((const float4*)k)[i];
    unsigned hA = pack_h2(kv.x, kv.y);
    unsigned hB = pack_h2(kv.z, kv.w);
    float hx, hy, hz, hw;
    unpack_h2(hA, hx, hy);
    unpack_h2(hB, hz, hw);
    unsigned mA = pack_h2(kv.x - hx, kv.y - hy);
    unsigned mB = pack_h2(kv.z - hz, kv.w - hw);
    ((uint2*)g_khi)[i]  = make_uint2(hA, hB);
    ((uint2*)g_kmid)[i] = make_uint2(mA, mB);
}

__device__ __forceinline__ void mma_f16(float& d0, float& d1, float& d2, float& d3,
                                        unsigned a0, unsigned a1, unsigned a2, unsigned a3,
                                        unsigned b0, unsigned b1) {
    asm("mma.sync.aligned.m16n8k16.row.col.f32.f16.f16.f32 "
        "{%0,%1,%2,%3}, {%4,%5,%6,%7}, {%8,%9}, {%0,%1,%2,%3};"
        : "+f"(d0), "+f"(d1), "+f"(d2), "+f"(d3)
        : "r"(a0), "r"(a1), "r"(a2), "r"(a3), "r"(b0), "r"(b1));
}

__device__ __forceinline__ void ldsm_x4(unsigned& r0, unsigned& r1, unsigned& r2, unsigned& r3,
                                        unsigned saddr) {
    asm volatile("ldmatrix.sync.aligned.m8n8.x4.shared.b16 {%0,%1,%2,%3}, [%4];"
                 : "=r"(r0), "=r"(r1), "=r"(r2), "=r"(r3) : "r"(saddr));
}

__device__ __forceinline__ void cp_async16(unsigned dst, const void* src) {
    asm volatile("cp.async.cg.shared.global [%0], [%1], 16;" :: "r"(dst), "l"(src) : "memory");
}
__device__ __forceinline__ void cp_commit() {
    asm volatile("cp.async.commit_group;" ::: "memory");
}
__device__ __forceinline__ void cp_wait0() {
    asm volatile("cp.async.wait_group 0;" ::: "memory");
}
__device__ __forceinline__ void pair_bar(int id) {
    asm volatile("bar.sync %0, 64;" :: "r"(id) : "memory");
}

// --------------------------------------------------------------------------
// One CTA = 16 q-rows of one batch, 512 threads / 16 warps.
// QK^T: fp16x2 3-term compensated MMA over a PER-WARP-PAIR cp.async
// pipeline. Pair p = warps {p, p+8} owns k-rows [16p, 16p+16); each pair
// copies its own 2KB slice per unit, waits on its own cp.async group, and
// syncs with a 64-thread named barrier -- pairs drift out of phase, hiding
// copy latency behind other pairs' MMAs. unit 2c = hi(c) -> slot0
// (hi*mid + hi*hi), unit 2c+1 = mid(c) -> slot1 (mid*hi + score STS).
// Sparsemax: Michelot + survivor compaction. Gather: ballot-compacted
// (p,j) pairs, 4-way MLP batched V loads.
// --------------------------------------------------------------------------
extern "C" __global__ void __launch_bounds__(NTHR, 2)
sparse_attn_kernel(const float* __restrict__ q,
                   const float* __restrict__ v,
                   const void*  __restrict__ maskp,
                   float* __restrict__ out,
                   float* __restrict__ attn,
                   int write_attn)
{
    extern __shared__ float sm[];
    unsigned* khi_s = (unsigned*)sm;               // slot0; slot1 at +KMID_BYTE_OFF
    float*    sc    = sm + KS_FLOATS;              // [QT][SCP]

    const int tid  = threadIdx.x;
    const int w    = tid >> 5;
    const int lane = tid & 31;
    const int b    = blockIdx.y;
    const int q0   = blockIdx.x * QT;
    const int mkind = g_mask_kind;

    // ---- Q subtile (w>>3) as f16x2 B fragments (hi + mid), 16 regs ----
    unsigned bh0[4], bh1[4], bm0[4], bm1[4];
    {
        const float* qb = q + ((size_t)(b * LQ + q0 + 8 * (w >> 3) + (lane >> 2))) * DH + 2 * (lane & 3);
        #pragma unroll
        for (int ks = 0; ks < 4; ++ks) {
            float2 p0 = *(const float2*)(qb + ks * 16);
            float2 p1 = *(const float2*)(qb + ks * 16 + 8);
            float f0 = p0.x * TEMP_INV, f1 = p0.y * TEMP_INV;
            float f2 = p1.x * TEMP_INV, f3 = p1.y * TEMP_INV;
            bh0[ks] = pack_h2(f0, f1);
            bh1[ks] = pack_h2(f2, f3);
            float h0, h1, h2, h3;
            unpack_h2(bh0[ks], h0, h1);
            unpack_h2(bh1[ks], h2, h3);
            bm0[ks] = pack_h2(f0 - h0, f1 - h1);
            bm1[ks] = pack_h2(f2 - h2, f3 - h3);
        }
    }
    const int pair = w & 7;
    const int kr0  = 16 * pair;
    const int ti   = (w >> 3) * 32 + lane;         // 0..63 within pair

    const unsigned sm_shared = (unsigned)__cvta_generic_to_shared(khi_s);

    // ldmatrix per-lane address (shared space), ks advances by 32 bytes
    unsigned lm_base;
    {
        int g  = lane >> 3;                        // matrix index 0..3
        int rl = lane & 7;
        int row = kr0 + rl + 8 * (g & 1);          // m1/m3 -> rows +8
        lm_base = sm_shared + (unsigned)(row * KP32 * 4 + (g >> 1) * 16);   // m2/m3 -> k+8
    }

    // per-thread pair-slice copy addresses: 16 rows x 128B per unit, 2 cp16/thread
    // flat = ti + 64*i : row = flat>>3 (0..15), c16 = flat&7
    unsigned cdst[2];
    int      csrc[2];
    #pragma unroll
    for (int i = 0; i < 2; ++i) {
        int flat = ti + 64 * i;
        int r = flat >> 3, c16 = flat & 7;
        cdst[i] = (unsigned)((kr0 + r) * KP32 * 4 + c16 * 16);
        csrc[i] = (kr0 + r) * 32 + c16 * 4;        // u32 offset within chunk base
    }

    // ---- QK^T per-pair pipeline over 16 units ----
    {
        // prologue: issue unit 0 (hi of chunk 0) for this pair's slice
        {
            const unsigned* gsrc = g_khi + (size_t)(b * LK) * 32;
            cp_async16(sm_shared + cdst[0], gsrc + csrc[0]);
            cp_async16(sm_shared + cdst[1], gsrc + csrc[1]);
            cp_commit();
        }

        float d0 = 0.f, d1 = 0.f, d2 = 0.f, d3 = 0.f;
        for (int u = 0; u < NU; ++u) {
            cp_wait0();                             // this pair's unit-u slice ready
            pair_bar(pair + 1);                     // both warps: prev compute done, copy visible
            if (u + 1 < NU) {
                int cn = (u + 1) >> 1;
                const unsigned* gsrc = (((u + 1) & 1) ? g_kmid : g_khi)
                                       + (size_t)(b * LK + cn * CHUNK) * 32;
                unsigned dstb = sm_shared + ((u + 1) & 1) * KMID_BYTE_OFF;
                cp_async16(dstb + cdst[0], gsrc + csrc[0]);
                cp_async16(dstb + cdst[1], gsrc + csrc[1]);
                cp_commit();
            }
            if (!(u & 1)) {
                // hi unit: hi*mid + hi*hi
                d0 = d1 = d2 = d3 = 0.f;
                #pragma unroll
                for (int ks = 0; ks < 4; ++ks) {
                    unsigned a0, a1, a2, a3;
                    ldsm_x4(a0, a1, a2, a3, lm_base + ks * 32);
                    mma_f16(d0, d1, d2, d3, a0, a1, a2, a3, bm0[ks], bm1[ks]);
                    mma_f16(d0, d1, d2, d3, a0, a1, a2, a3, bh0[ks], bh1[ks]);
                }
            } else {
                // mid unit: mid*hi, then score epilogue for chunk c
                #pragma unroll
                for (int ks = 0; ks < 4; ++ks) {
                    unsigned a0, a1, a2, a3;
                    ldsm_x4(a0, a1, a2, a3, lm_base + KMID_BYTE_OFF + ks * 32);
                    mma_f16(d0, d1, d2, d3, a0, a1, a2, a3, bh0[ks], bh1[ks]);
                }
                int c  = u >> 1;
                int kg = c * CHUNK + kr0 + (lane >> 2);
                int qc = 8 * (w >> 3) + 2 * (lane & 3);
                sc[qc * SCP + kg]           = d0;
                sc[(qc + 1) * SCP + kg]     = d1;
                sc[qc * SCP + kg + 8]       = d2;
                sc[(qc + 1) * SCP + kg + 8] = d3;
            }
        }
    }
    __syncthreads();

    // ---- mask pass, 16-byte vectorized ----
    {
        size_t mbase = ((size_t)b * LQ + q0) * LK;
        if (mkind == 0) {
            const uint4* m4 = (const uint4*)((const unsigned char*)maskp + mbase);
            #pragma unroll
            for (int it = 0; it < (QT * LK) / 16 / NTHR; ++it) {
                int idx  = tid + NTHR * it;
                uint4 u  = m4[idx];
                int base = idx * 16;
                float* srow = sc + (base >> 10) * SCP + (base & 1023);
                #pragma unroll
                for (int bt = 0; bt < 4; ++bt) {
                    unsigned uu = (&u.x)[bt];
                    if (uu & 0x000000FFu) srow[bt * 4 + 0] = REMOVED;
                    if (uu & 0x0000FF00u) srow[bt * 4 + 1] = REMOVED;
                    if (uu & 0x00FF0000u) srow[bt * 4 + 2] = REMOVED;
                    if (uu & 0xFF000000u) srow[bt * 4 + 3] = REMOVED;
                }
            }
        } else {
            const uint4* m4 = (const uint4*)((const unsigned*)maskp + mbase);
            #pragma unroll
            for (int it = 0; it < (QT * LK) / 4 / NTHR; ++it) {
                int idx  = tid + NTHR * it;
                uint4 u  = m4[idx];
                int base = idx * 4;
                float* srow = sc + (base >> 10) * SCP + (base & 1023);
                if (u.x) srow[0] = REMOVED;
                if (u.y) srow[1] = REMOVED;
                if (u.z) srow[2] = REMOVED;
                if (u.w) srow[3] = REMOVED;
            }
        }
    }
    __syncthreads();   // also fences K-slot scratch reuse (GEMM reads done)

    // ---- sparsemax (warp w owns row w): Michelot with survivor compaction ----
    const float* zr = sc + w * SCP;
    float* wsc = sm + w * WSCR;            // per-warp scratch in dead K region
    const unsigned lt = (1u << lane) - 1u;

    float S = 0.0f; int Cl = 0;
    #pragma unroll
    for (int t4 = 0; t4 < 8; ++t4) {
        float4 zv = *(const float4*)(zr + 4 * lane + 128 * t4);
        if (zv.x > CUTV) { S += zv.x; Cl++; }
        if (zv.y > CUTV) { S += zv.y; Cl++; }
        if (zv.z > CUTV) { S += zv.z; Cl++; }
        if (zv.w > CUTV) { S += zv.w; Cl++; }
    }
    #pragma unroll
    for (int o = 16; o; o >>= 1) S += __shfl_xor_sync(0xFFFFFFFFu, S, o);
    int C = __reduce_add_sync(0xFFFFFFFFu, Cl);

    float tau;
    if (C > 0) {
        tau = (S - 1.0f) / (float)C;
        float s2 = 0.0f; int c2l = 0; int cnt = 0;
        #pragma unroll
        for (int t4 = 0; t4 < 8; ++t4) {
            float4 zv = *(const float4*)(zr + 4 * lane + 128 * t4);
            #pragma unroll
            for (int e = 0; e < 4; ++e) {
                float ze = (&zv.x)[e];
                bool a = ze > tau;
                unsigned bb = __ballot_sync(0xFFFFFFFFu, a);
                if (a) {
                    int ps = cnt + __popc(bb & lt);
                    if (ps < CAPS) wsc[ps] = ze;
                    s2 += ze; c2l++;
                }
                cnt += __popc(bb);
            }
        }
        int c2 = __reduce_add_sync(0xFFFFFFFFu, c2l);
        #pragma unroll
        for (int o = 16; o; o >>= 1) s2 += __shfl_xor_sync(0xFFFFFFFFu, s2, o);

        if (c2 != C) {
            if (cnt <= CAPS) {
                __syncwarp();
                S = s2; C = c2;
                tau = (S - 1.0f) / (float)C;
                for (int iter = 0; iter < 64; ++iter) {
                    float s3 = 0.0f; int c3l = 0;
                    for (int i = lane; i < cnt; i += 32) {
                        float z3 = wsc[i];
                        if (z3 > tau) { s3 += z3; c3l++; }
                    }
                    int c3 = __reduce_add_sync(0xFFFFFFFFu, c3l);
                    #pragma unroll
                    for (int o = 16; o; o >>= 1) s3 += __shfl_xor_sync(0xFFFFFFFFu, s3, o);
                    if (c3 == C) break;
                    S = s3; C = c3;
                    tau = (S - 1.0f) / (float)C;
                }
            } else {
                S = s2; C = c2;
                tau = (S - 1.0f) / (float)C;
                for (int iter = 0; iter < 64; ++iter) {
                    float s3 = 0.0f; int c3l = 0;
                    #pragma unroll
                    for (int t4 = 0; t4 < 8; ++t4) {
                        float4 zv = *(const float4*)(zr + 4 * lane + 128 * t4);
                        if (zv.x > tau) { s3 += zv.x; c3l++; }
                        if (zv.y > tau) { s3 += zv.y; c3l++; }
                        if (zv.z > tau) { s3 += zv.z; c3l++; }
                        if (zv.w > tau) { s3 += zv.w; c3l++; }
                    }
                    int c3 = __reduce_add_sync(0xFFFFFFFFu, c3l);
                    #pragma unroll
                    for (int o = 16; o; o >>= 1) s3 += __shfl_xor_sync(0xFFFFFFFFu, s3, o);
                    if (c3 == C) break;
                    S = s3; C = c3;
                    tau = (S - 1.0f) / (float)C;
                }
            }
        }
    } else {
        tau = 1.0e30f;                     // fully-masked row
    }
    __syncwarp();

    // ---- probabilities -> attn (float4 stores) + ballot-compacted (p,j) pairs ----
    const float2* vb2 = (const float2*)(v + (size_t)b * LK * DH);
    float* cp = wsc;                       // reuse scratch for (p, j) pairs
    float* arow = attn + ((size_t)(b * LQ + q0 + w)) * LK;
    float2 acc2 = make_float2(0.0f, 0.0f);
    int cnt = 0;

    #pragma unroll
    for (int tt = 0; tt < 8; ++tt) {
        const int j0 = 4 * lane + 128 * tt;
        float4 zv = *(const float4*)(zr + j0);
        float4 pv;
        pv.x = fmaxf(zv.x - tau, 0.0f);
        pv.y = fmaxf(zv.y - tau, 0.0f);
        pv.z = fmaxf(zv.z - tau, 0.0f);
        pv.w = fmaxf(zv.w - tau, 0.0f);
        if (write_attn) *(float4*)(arow + j0) = pv;

        unsigned bb0 = __ballot_sync(0xFFFFFFFFu, pv.x > 0.0f);
        unsigned bb1 = __ballot_sync(0xFFFFFFFFu, pv.y > 0.0f);
        unsigned bb2 = __ballot_sync(0xFFFFFFFFu, pv.z > 0.0f);
        unsigned bb3 = __ballot_sync(0xFFFFFFFFu, pv.w > 0.0f);
        int base0 = cnt;
        int base1 = base0 + __popc(bb0);
        int base2 = base1 + __popc(bb1);
        int base3 = base2 + __popc(bb2);
        cnt       = base3 + __popc(bb3);

        int ps;
        ps = base0 + __popc(bb0 & lt);
        if (pv.x > 0.0f && ps < CAPG) { cp[2 * ps] = pv.x; cp[2 * ps + 1] = __int_as_float(j0); }
        ps = base1 + __popc(bb1 & lt);
        if (pv.y > 0.0f && ps < CAPG) { cp[2 * ps] = pv.y; cp[2 * ps + 1] = __int_as_float(j0 + 1); }
        ps = base2 + __popc(bb2 & lt);
        if (pv.z > 0.0f && ps < CAPG) { cp[2 * ps] = pv.z; cp[2 * ps + 1] = __int_as_float(j0 + 2); }
        ps = base3 + __popc(bb3 & lt);
        if (pv.w > 0.0f && ps < CAPG) { cp[2 * ps] = pv.w; cp[2 * ps + 1] = __int_as_float(j0 + 3); }

        if (cnt > CAPG) {
            #pragma unroll
            for (int e = 0; e < 4; ++e) {
                float pe = (&pv.x)[e];
                unsigned bb = (e == 0) ? bb0 : (e == 1) ? bb1 : (e == 2) ? bb2 : bb3;
                int be     = (e == 0) ? base0 : (e == 1) ? base1 : (e == 2) ? base2 : base3;
                unsigned ovf = __ballot_sync(0xFFFFFFFFu,
                                             pe > 0.0f && (be + __popc(bb & lt)) >= CAPG);
                while (ovf) {
                    int src = __ffs(ovf) - 1;
                    ovf &= ovf - 1;
                    float pj = __shfl_sync(0xFFFFFFFFu, pe, src);
                    int j = 4 * src + 128 * tt + e;
                    const float2 vv = vb2[j * 32 + lane];
                    acc2.x += pj * vv.x;
                    acc2.y += pj * vv.y;
                }
            }
        }
    }
    __syncwarp();

    // ---- batched V gather: 4 independent loads in flight ----
    {
        const int cn = cnt < CAPG ? cnt : CAPG;
        int i = 0;
        for (; i + 4 <= cn; i += 4) {
            float4 e0 = *(const float4*)(cp + 2 * i);
            float4 e1 = *(const float4*)(cp + 2 * i + 4);
            const float2 v0 = vb2[__float_as_int(e0.y) * 32 + lane];
            const float2 v1 = vb2[__float_as_int(e0.w) * 32 + lane];
            const float2 v2 = vb2[__float_as_int(e1.y) * 32 + lane];
            const float2 v3 = vb2[__float_as_int(e1.w) * 32 + lane];
            acc2.x += e0.x * v0.x;  acc2.y += e0.x * v0.y;
            acc2.x += e0.z * v1.x;  acc2.y += e0.z * v1.y;
            acc2.x += e1.x * v2.x;  acc2.y += e1.x * v2.y;
            acc2.x += e1.z * v3.x;  acc2.y += e1.z * v3.y;
        }
        for (; i < cn; ++i) {
            float p = cp[2 * i];
            int  j  = __float_as_int(cp[2 * i + 1]);
            const float2 vv = vb2[j * 32 + lane];
            acc2.x += p * vv.x;
            acc2.y += p * vv.y;
        }
    }

    *(float2*)(out + ((size_t)(b * LQ + q0 + w)) * DH + 2 * lane) = acc2;
}

// --------------------------------------------------------------------------
extern "C" void kernel_launch(void* const* d_in, const int* in_sizes, int n_in,
                              void* d_out, int out_size) {
    const float* q = (const float*)d_in[0];
    const float* k = (const float*)d_in[1];
    const float* v = (const float*)d_in[2];
    const void*  m = d_in[3];

    float* out = (float*)d_out;
    long long out_elems  = (long long)B_ * LQ * DH;
    long long attn_elems = (long long)B_ * LQ * LK;
    int write_attn = ((long long)out_size >= out_elems + attn_elems) ? 1 : 0;
    float* attn = out + (size_t)out_elems;

    prep_kernel<<<KELEMS / 4 / 256, 256>>>(k, (const unsigned char*)m);

    cudaFuncSetAttribute(sparse_attn_kernel,
                         cudaFuncAttributeMaxDynamicSharedMemorySize, SMEM_BYTES);

    dim3 grid(LQ / QT, B_);
    sparse_attn_kernel<<<grid, NTHR, SMEM_BYTES>>>(q, v, m, out, attn, write_attn);
}

// round 15
// speedup vs baseline: 1.2849x; 1.0983x over previous
#include <cuda_runtime.h>
#include <cstdint>
#include <cstddef>

#define B_      64
#define LQ      1024
#define LK      1024
#define DH      64
#define QT      16
#define CHUNK   128
#define NCH     (LK / CHUNK)   // 8
#define NU      (2 * NCH)      // 16 pipeline units (hi/mid per chunk)
#define NTHR    512
#define KP32    36             // K smem pitch in u32: bank=(4r+u)%32 -> conflict-free
#define SCP     1028           // sc pitch: score STS conflict-free
#define CAPP    288            // (z,j)/(p,j) pair capacity per warp (wsc = 576 floats)
#define TEMP_INV 0.125f

// smem: slot0 hi[128*36 u32] | slot1 mid[128*36 u32] (=9216 floats; reused as 16x576 scratch) | sc[16*1028]
#define KS_FLOATS   (2 * CHUNK * KP32)     // 9216
#define SC_FLOATS   (QT * SCP)             // 16448
#define SMEM_FLOATS (KS_FLOATS + SC_FLOATS)
#define SMEM_BYTES  (SMEM_FLOATS * 4)
#define WSCR        576                    // per-warp scratch floats (16*576 = 9216)
#define KMID_BYTE_OFF (CHUNK * KP32 * 4)   // byte offset of slot1 from slot0

#define KELEMS  (B_ * LK * DH)             // 4,194,304
#define KU32S   (KELEMS / 2)               // f16x2 words per split array

__device__ int      g_mask_kind;           // 0 = uint8/bool, 1 = int32, 2 = float32
__device__ unsigned g_khi[KU32S];          // K fp16 hi  (f16x2-packed), built per launch
__device__ unsigned g_kmid[KU32S];         // K fp16 mid residual

// pack two fp32 -> f16x2 (lo = x, hi = y)
__device__ __forceinline__ unsigned pack_h2(float x, float y) {
    unsigned r;
    asm("cvt.rn.f16x2.f32 %0, %1, %2;" : "=r"(r) : "f"(y), "f"(x));
    return r;
}
// unpack f16x2 -> two fp32
__device__ __forceinline__ void unpack_h2(unsigned p, float& x, float& y) {
    asm("{ .reg .f16 l, h; mov.b32 {l, h}, %2; cvt.f32.f16 %0, l; cvt.f32.f16 %1, h; }"
        : "=f"(x), "=f"(y) : "r"(p));
}

// ---- prep: K fp16 hi/mid split (byte-neutral) + mask-dtype detection ----
__global__ void prep_kernel(const float* __restrict__ k, const unsigned char* __restrict__ m) {
    if (blockIdx.x == 0 && threadIdx.x < 32) {
        uint4 u = ((const uint4*)m)[threadIdx.x];   // 512 bytes sample
        unsigned fl = 0;
        #pragma unroll
        for (int bt = 0; bt < 4; ++bt) {
            unsigned uu = (&u.x)[bt];
            if (uu & 0x000000FFu) fl |= 1u;
            if (uu & 0x0000FF00u) fl |= 2u;
            if (uu & 0x00FF0000u) fl |= 4u;
            if (uu & 0xFF000000u) fl |= 8u;
        }
        fl = __reduce_or_sync(0xFFFFFFFFu, fl);
        if (threadIdx.x == 0) {
            int kind;
            if ((fl & 0xEu) == 0)                 kind = 1;  // int32
            else if ((fl & 1u) == 0 && (fl & 8u)) kind = 2;  // float32
            else                                  kind = 0;  // uint8 / bool
            g_mask_kind = kind;
        }
    }
    int i = blockIdx.x * 256 + threadIdx.x;        // float4 index
    float4 kv = ((const float4*)k)[i];
    unsigned hA = pack_h2(kv.x, kv.y);
    unsigned hB = pack_h2(kv.z, kv.w);
    float hx, hy, hz, hw;
    unpack_h2(hA, hx, hy);
    unpack_h2(hB, hz, hw);
    unsigned mA = pack_h2(kv.x - hx, kv.y - hy);
    unsigned mB = pack_h2(kv.z - hz, kv.w - hw);
    ((uint2*)g_khi)[i]  = make_uint2(hA, hB);
    ((uint2*)g_kmid)[i] = make_uint2(mA, mB);
}

__device__ __forceinline__ void mma_f16(float& d0, float& d1, float& d2, float& d3,
                                        unsigned a0, unsigned a1, unsigned a2, unsigned a3,
                                        unsigned b0, unsigned b1) {
    asm("mma.sync.aligned.m16n8k16.row.col.f32.f16.f16.f32 "
        "{%0,%1,%2,%3}, {%4,%5,%6,%7}, {%8,%9}, {%0,%1,%2,%3};"
        : "+f"(d0), "+f"(d1), "+f"(d2), "+f"(d3)
        : "r"(a0), "r"(a1), "r"(a2), "r"(a3), "r"(b0), "r"(b1));
}

__device__ __forceinline__ void ldsm_x4(unsigned& r0, unsigned& r1, unsigned& r2, unsigned& r3,
                                        unsigned saddr) {
    asm volatile("ldmatrix.sync.aligned.m8n8.x4.shared.b16 {%0,%1,%2,%3}, [%4];"
                 : "=r"(r0), "=r"(r1), "=r"(r2), "=r"(r3) : "r"(saddr));
}

__device__ __forceinline__ void cp_async16(unsigned dst, const void* src) {
    asm volatile("cp.async.cg.shared.global [%0], [%1], 16;" :: "r"(dst), "l"(src) : "memory");
}
__device__ __forceinline__ void cp_commit() {
    asm volatile("cp.async.commit_group;" ::: "memory");
}
__device__ __forceinline__ void cp_wait0() {
    asm volatile("cp.async.wait_group 0;" ::: "memory");
}
__device__ __forceinline__ void pair_bar(int id) {
    asm volatile("bar.sync %0, 64;" :: "r"(id) : "memory");
}

// load 4 mask flags for elements [basei, basei+4) of one score row
__device__ __forceinline__ void mask4(const unsigned char* mrow8, const unsigned* mrow32,
                                      int mkind, int basei,
                                      bool& m0, bool& m1, bool& m2, bool& m3) {
    if (mkind == 0) {
        unsigned mu = *(const unsigned*)(mrow8 + basei);
        m0 = (mu & 0x000000FFu) != 0; m1 = (mu & 0x0000FF00u) != 0;
        m2 = (mu & 0x00FF0000u) != 0; m3 = (mu & 0xFF000000u) != 0;
    } else {
        uint4 mu = *(const uint4*)(mrow32 + basei);
        m0 = mu.x != 0; m1 = mu.y != 0; m2 = mu.z != 0; m3 = mu.w != 0;
    }
}

// --------------------------------------------------------------------------
// One CTA = 16 q-rows of one batch, 512 threads / 16 warps.
// QK^T: fp16x2 3-term compensated MMA over per-warp-pair cp.async pipeline
// (unchanged from R14). Sparsemax: mask folded into the scans (no mask pass,
// no sentinel), tau0-compaction stores (z,j) PAIRS -> iterations AND the
// V-gather list come from the same compact list. attn row = zero-fill +
// scatter of support probabilities (no third full pass). Overflow (>CAPP
// entries above tau0) falls back to stateless scans + old ballot p-pass.
// --------------------------------------------------------------------------
extern "C" __global__ void __launch_bounds__(NTHR, 2)
sparse_attn_kernel(const float* __restrict__ q,
                   const float* __restrict__ v,
                   const void*  __restrict__ maskp,
                   float* __restrict__ out,
                   float* __restrict__ attn,
                   int write_attn)
{
    extern __shared__ float sm[];
    unsigned* khi_s = (unsigned*)sm;               // slot0; slot1 at +KMID_BYTE_OFF
    float*    sc    = sm + KS_FLOATS;              // [QT][SCP]

    const int tid  = threadIdx.x;
    const int w    = tid >> 5;
    const int lane = tid & 31;
    const int b    = blockIdx.y;
    const int q0   = blockIdx.x * QT;
    const int mkind = g_mask_kind;

    // ---- Q subtile (w>>3) as f16x2 B fragments (hi + mid), 16 regs ----
    unsigned bh0[4], bh1[4], bm0[4], bm1[4];
    {
        const float* qb = q + ((size_t)(b * LQ + q0 + 8 * (w >> 3) + (lane >> 2))) * DH + 2 * (lane & 3);
        #pragma unroll
        for (int ks = 0; ks < 4; ++ks) {
            float2 p0 = *(const float2*)(qb + ks * 16);
            float2 p1 = *(const float2*)(qb + ks * 16 + 8);
            float f0 = p0.x * TEMP_INV, f1 = p0.y * TEMP_INV;
            float f2 = p1.x * TEMP_INV, f3 = p1.y * TEMP_INV;
            bh0[ks] = pack_h2(f0, f1);
            bh1[ks] = pack_h2(f2, f3);
            float h0, h1, h2, h3;
            unpack_h2(bh0[ks], h0, h1);
            unpack_h2(bh1[ks], h2, h3);
            bm0[ks] = pack_h2(f0 - h0, f1 - h1);
            bm1[ks] = pack_h2(f2 - h2, f3 - h3);
        }
    }
    const int pair = w & 7;
    const int kr0  = 16 * pair;
    const int ti   = (w >> 3) * 32 + lane;         // 0..63 within pair

    const unsigned sm_shared = (unsigned)__cvta_generic_to_shared(khi_s);

    // ldmatrix per-lane address (shared space), ks advances by 32 bytes
    unsigned lm_base;
    {
        int g  = lane >> 3;                        // matrix index 0..3
        int rl = lane & 7;
        int row = kr0 + rl + 8 * (g & 1);          // m1/m3 -> rows +8
        lm_base = sm_shared + (unsigned)(row * KP32 * 4 + (g >> 1) * 16);   // m2/m3 -> k+8
    }

    // per-thread pair-slice copy addresses: 16 rows x 128B per unit, 2 cp16/thread
    unsigned cdst[2];
    int      csrc[2];
    #pragma unroll
    for (int i = 0; i < 2; ++i) {
        int flat = ti + 64 * i;
        int r = flat >> 3, c16 = flat & 7;
        cdst[i] = (unsigned)((kr0 + r) * KP32 * 4 + c16 * 16);
        csrc[i] = (kr0 + r) * 32 + c16 * 4;        // u32 offset within chunk base
    }

    // ---- QK^T per-pair pipeline over 16 units ----
    {
        {
            const unsigned* gsrc = g_khi + (size_t)(b * LK) * 32;
            cp_async16(sm_shared + cdst[0], gsrc + csrc[0]);
            cp_async16(sm_shared + cdst[1], gsrc + csrc[1]);
            cp_commit();
        }

        float d0 = 0.f, d1 = 0.f, d2 = 0.f, d3 = 0.f;
        for (int u = 0; u < NU; ++u) {
            cp_wait0();
            pair_bar(pair + 1);
            if (u + 1 < NU) {
                int cn = (u + 1) >> 1;
                const unsigned* gsrc = (((u + 1) & 1) ? g_kmid : g_khi)
                                       + (size_t)(b * LK + cn * CHUNK) * 32;
                unsigned dstb = sm_shared + ((u + 1) & 1) * KMID_BYTE_OFF;
                cp_async16(dstb + cdst[0], gsrc + csrc[0]);
                cp_async16(dstb + cdst[1], gsrc + csrc[1]);
                cp_commit();
            }
            if (!(u & 1)) {
                d0 = d1 = d2 = d3 = 0.f;
                #pragma unroll
                for (int ks = 0; ks < 4; ++ks) {
                    unsigned a0, a1, a2, a3;
                    ldsm_x4(a0, a1, a2, a3, lm_base + ks * 32);
                    mma_f16(d0, d1, d2, d3, a0, a1, a2, a3, bm0[ks], bm1[ks]);
                    mma_f16(d0, d1, d2, d3, a0, a1, a2, a3, bh0[ks], bh1[ks]);
                }
            } else {
                #pragma unroll
                for (int ks = 0; ks < 4; ++ks) {
                    unsigned a0, a1, a2, a3;
                    ldsm_x4(a0, a1, a2, a3, lm_base + KMID_BYTE_OFF + ks * 32);
                    mma_f16(d0, d1, d2, d3, a0, a1, a2, a3, bh0[ks], bh1[ks]);
                }
                int c  = u >> 1;
                int kg = c * CHUNK + kr0 + (lane >> 2);
                int qc = 8 * (w >> 3) + 2 * (lane & 3);
                sc[qc * SCP + kg]           = d0;
                sc[(qc + 1) * SCP + kg]     = d1;
                sc[qc * SCP + kg + 8]       = d2;
                sc[(qc + 1) * SCP + kg + 8] = d3;
            }
        }
    }
    __syncthreads();   // scores visible; K slots become per-warp scratch

    // ---- sparsemax (warp w owns row w), mask folded into scans ----
    const float* zr = sc + w * SCP;
    float* wsc = sm + w * WSCR;
    const unsigned lt = (1u << lane) - 1u;
    const size_t rowoff = (size_t)(b * LQ + q0 + w) * LK;
    const unsigned char* mrow8  = (const unsigned char*)maskp + rowoff;
    const unsigned*      mrow32 = (const unsigned*)maskp + rowoff;

    // scan1: S, C over unmasked entries
    float S = 0.0f; int Cl = 0;
    #pragma unroll
    for (int t4 = 0; t4 < 8; ++t4) {
        int basei = 4 * lane + 128 * t4;
        float4 zv = *(const float4*)(zr + basei);
        bool m0, m1, m2, m3;
        mask4(mrow8, mrow32, mkind, basei, m0, m1, m2, m3);
        if (!m0) { S += zv.x; Cl++; }
        if (!m1) { S += zv.y; Cl++; }
        if (!m2) { S += zv.z; Cl++; }
        if (!m3) { S += zv.w; Cl++; }
    }
    #pragma unroll
    for (int o = 16; o; o >>= 1) S += __shfl_xor_sync(0xFFFFFFFFu, S, o);
    int C = __reduce_add_sync(0xFFFFFFFFu, Cl);

    float tau = 1.0e30f;
    int   cnt = 0;
    bool  listok = true;

    if (C > 0) {
        tau = (S - 1.0f) / (float)C;
        // scan2: compact (z, j) pairs with z > tau0, unmasked
        float s2 = 0.0f; int c2l = 0;
        #pragma unroll
        for (int t4 = 0; t4 < 8; ++t4) {
            int basei = 4 * lane + 128 * t4;
            float4 zv = *(const float4*)(zr + basei);
            bool mm[4];
            mask4(mrow8, mrow32, mkind, basei, mm[0], mm[1], mm[2], mm[3]);
            #pragma unroll
            for (int e = 0; e < 4; ++e) {
                float z = (&zv.x)[e];
                bool a = !mm[e] && z > tau;
                unsigned bb = __ballot_sync(0xFFFFFFFFu, a);
                if (a) {
                    int ps = cnt + __popc(bb & lt);
                    if (ps < CAPP) {
                        wsc[2 * ps]     = z;
                        wsc[2 * ps + 1] = __int_as_float(basei + e);
                    }
                    s2 += z; c2l++;
                }
                cnt += __popc(bb);
            }
        }
        int c2 = __reduce_add_sync(0xFFFFFFFFu, c2l);
        #pragma unroll
        for (int o = 16; o; o >>= 1) s2 += __shfl_xor_sync(0xFFFFFFFFu, s2, o);

        if (cnt <= CAPP) {
            if (c2 != C) {
                __syncwarp();
                S = s2; C = c2;
                tau = (S - 1.0f) / (float)C;
                for (int iter = 0; iter < 64; ++iter) {
                    float s3 = 0.0f; int c3l = 0;
                    for (int i = lane; i < cnt; i += 32) {
                        float2 e2 = *(const float2*)(wsc + 2 * i);
                        if (e2.x > tau) { s3 += e2.x; c3l++; }
                    }
                    int c3 = __reduce_add_sync(0xFFFFFFFFu, c3l);
                    #pragma unroll
                    for (int o = 16; o; o >>= 1) s3 += __shfl_xor_sync(0xFFFFFFFFu, s3, o);
                    if (c3 == C) break;
                    S = s3; C = c3;
                    tau = (S - 1.0f) / (float)C;
                }
            }
        } else {
            listok = false;
            if (c2 != C) {
                S = s2; C = c2;
                tau = (S - 1.0f) / (float)C;
                for (int iter = 0; iter < 64; ++iter) {
                    float s3 = 0.0f; int c3l = 0;
                    #pragma unroll
                    for (int t4 = 0; t4 < 8; ++t4) {
                        int basei = 4 * lane + 128 * t4;
                        float4 zv = *(const float4*)(zr + basei);
                        bool mm[4];
                        mask4(mrow8, mrow32, mkind, basei, mm[0], mm[1], mm[2], mm[3]);
                        #pragma unroll
                        for (int e = 0; e < 4; ++e) {
                            float z = (&zv.x)[e];
                            if (!mm[e] && z > tau) { s3 += z; c3l++; }
                        }
                    }
                    int c3 = __reduce_add_sync(0xFFFFFFFFu, c3l);
                    #pragma unroll
                    for (int o = 16; o; o >>= 1) s3 += __shfl_xor_sync(0xFFFFFFFFu, s3, o);
                    if (c3 == C) break;
                    S = s3; C = c3;
                    tau = (S - 1.0f) / (float)C;
                }
            }
        }
    }
    __syncwarp();

    // ---- epilogue: attn row + sparse attn@V ----
    const float2* vb2 = (const float2*)(v + (size_t)b * LK * DH);
    float* arow = attn + rowoff;
    float2 acc2 = make_float2(0.0f, 0.0f);

    if (listok) {
        if (write_attn) {
            const float4 z4 = make_float4(0.f, 0.f, 0.f, 0.f);
            #pragma unroll
            for (int t = 0; t < 8; ++t)
                *(float4*)(arow + 4 * lane + 128 * t) = z4;
        }
        __syncwarp();   // zero-fill done before scatter (cross-lane same addresses)

        // final support compaction (in-place) + attn scatter
        int ns = 0;
        for (int basei = 0; basei < cnt; basei += 32) {
            int i = basei + lane;
            float z = 0.f; int j = 0;
            bool valid = i < cnt;
            if (valid) {
                float2 e2 = *(const float2*)(wsc + 2 * i);
                z = e2.x; j = __float_as_int(e2.y);
            }
            float p = z - tau;
            bool a = valid && p > 0.0f;
            unsigned bb = __ballot_sync(0xFFFFFFFFu, a);
            __syncwarp();            // all reads of this chunk before in-place writes
            if (a) {
                int ps = ns + __popc(bb & lt);
                wsc[2 * ps]     = p;
                wsc[2 * ps + 1] = __int_as_float(j);
                if (write_attn) arow[j] = p;
            }
            ns += __popc(bb);
        }
        __syncwarp();

        // batched V gather: 4 independent loads in flight
        int i = 0;
        for (; i + 4 <= ns; i += 4) {
            float4 e0 = *(const float4*)(wsc + 2 * i);
            float4 e1 = *(const float4*)(wsc + 2 * i + 4);
            const float2 v0 = vb2[__float_as_int(e0.y) * 32 + lane];
            const float2 v1 = vb2[__float_as_int(e0.w) * 32 + lane];
            const float2 v2 = vb2[__float_as_int(e1.y) * 32 + lane];
            const float2 v3 = vb2[__float_as_int(e1.w) * 32 + lane];
            acc2.x += e0.x * v0.x;  acc2.y += e0.x * v0.y;
            acc2.x += e0.z * v1.x;  acc2.y += e0.z * v1.y;
            acc2.x += e1.x * v2.x;  acc2.y += e1.x * v2.y;
            acc2.x += e1.z * v3.x;  acc2.y += e1.z * v3.y;
        }
        for (; i < ns; ++i) {
            float p = wsc[2 * i];
            int  j  = __float_as_int(wsc[2 * i + 1]);
            const float2 vv = vb2[j * 32 + lane];
            acc2.x += p * vv.x;
            acc2.y += p * vv.y;
        }
    } else {
        // fallback (rare, support@tau0 > CAPP): ballot-compaction p-pass, mask inline
        float* cp = wsc;
        int gcnt = 0;
        #pragma unroll
        for (int tt = 0; tt < 8; ++tt) {
            const int j0 = 4 * lane + 128 * tt;
            float4 zv = *(const float4*)(zr + j0);
            bool mm[4];
            mask4(mrow8, mrow32, mkind, j0, mm[0], mm[1], mm[2], mm[3]);
            float4 pv;
            pv.x = mm[0] ? 0.f : fmaxf(zv.x - tau, 0.0f);
            pv.y = mm[1] ? 0.f : fmaxf(zv.y - tau, 0.0f);
            pv.z = mm[2] ? 0.f : fmaxf(zv.z - tau, 0.0f);
            pv.w = mm[3] ? 0.f : fmaxf(zv.w - tau, 0.0f);
            if (write_attn) *(float4*)(arow + j0) = pv;

            #pragma unroll
            for (int e = 0; e < 4; ++e) {
                float pe = (&pv.x)[e];
                bool a = pe > 0.0f;
                unsigned bb = __ballot_sync(0xFFFFFFFFu, a);
                int base = gcnt;
                if (a) {
                    int ps = base + __popc(bb & lt);
                    if (ps < CAPP) {
                        cp[2 * ps]     = pe;
                        cp[2 * ps + 1] = __int_as_float(j0 + e);
                    } else {
                        // overflow entries: direct serial accumulate
                        const float2 vv = vb2[(j0 + e) * 32 + lane];
                        acc2.x += pe * vv.x;
                        acc2.y += pe * vv.y;
                    }
                }
                gcnt += __popc(bb);
            }
        }
        __syncwarp();
        const int cn = gcnt < CAPP ? gcnt : CAPP;
        int i = 0;
        for (; i + 4 <= cn; i += 4) {
            float4 e0 = *(const float4*)(cp + 2 * i);
            float4 e1 = *(const float4*)(cp + 2 * i + 4);
            const float2 v0 = vb2[__float_as_int(e0.y) * 32 + lane];
            const float2 v1 = vb2[__float_as_int(e0.w) * 32 + lane];
            const float2 v2 = vb2[__float_as_int(e1.y) * 32 + lane];
            const float2 v3 = vb2[__float_as_int(e1.w) * 32 + lane];
            acc2.x += e0.x * v0.x;  acc2.y += e0.x * v0.y;
            acc2.x += e0.z * v1.x;  acc2.y += e0.z * v1.y;
            acc2.x += e1.x * v2.x;  acc2.y += e1.x * v2.y;
            acc2.x += e1.z * v3.x;  acc2.y += e1.z * v3.y;
        }
        for (; i < cn; ++i) {
            float p = cp[2 * i];
            int  j  = __float_as_int(cp[2 * i + 1]);
            const float2 vv = vb2[j * 32 + lane];
            acc2.x += p * vv.x;
            acc2.y += p * vv.y;
        }
    }

    *(float2*)(out + ((size_t)(b * LQ + q0 + w)) * DH + 2 * lane) = acc2;
}

// --------------------------------------------------------------------------
extern "C" void kernel_launch(void* const* d_in, const int* in_sizes, int n_in,
                              void* d_out, int out_size) {
    const float* q = (const float*)d_in[0];
    const float* k = (const float*)d_in[1];
    const float* v = (const float*)d_in[2];
    const void*  m = d_in[3];

    float* out = (float*)d_out;
    long long out_elems  = (long long)B_ * LQ * DH;
    long long attn_elems = (long long)B_ * LQ * LK;
    int write_attn = ((long long)out_size >= out_elems + attn_elems) ? 1 : 0;
    float* attn = out + (size_t)out_elems;

    prep_kernel<<<KELEMS / 4 / 256, 256>>>(k, (const unsigned char*)m);

    cudaFuncSetAttribute(sparse_attn_kernel,
                         cudaFuncAttributeMaxDynamicSharedMemorySize, SMEM_BYTES);

    dim3 grid(LQ / QT, B_);
    sparse_attn_kernel<<<grid, NTHR, SMEM_BYTES>>>(q, v, m, out, attn, write_attn);
}

// round 16
// speedup vs baseline: 1.2921x; 1.0056x over previous
#include <cuda_runtime.h>
#include <cstdint>
#include <cstddef>

#define B_      64
#define LQ      1024
#define LK      1024
#define DH      64
#define QT      16
#define CHUNK   128
#define NCH     (LK / CHUNK)   // 8
#define NU      (2 * NCH)      // 16 pipeline units (hi/mid per chunk)
#define NTHR    512
#define KP32    36             // K smem pitch in u32: bank=(4r+u)%32 -> conflict-free
#define SCP     1028           // sc pitch: score STS conflict-free
#define CAPP    288            // (z,j)/(p,j) pair capacity per warp (wsc = 576 floats)
#define TEMP_INV 0.125f

// smem: slot0 hi[128*36 u32] | slot1 mid[128*36 u32] (=9216 floats; reused as 16x576 scratch) | sc[16*1028]
#define KS_FLOATS   (2 * CHUNK * KP32)     // 9216
#define SC_FLOATS   (QT * SCP)             // 16448
#define SMEM_FLOATS (KS_FLOATS + SC_FLOATS)
#define SMEM_BYTES  (SMEM_FLOATS * 4)
#define WSCR        576                    // per-warp scratch floats (16*576 = 9216)
#define KMID_BYTE_OFF (CHUNK * KP32 * 4)   // byte offset of slot1 from slot0

#define KELEMS  (B_ * LK * DH)             // 4,194,304
#define KU32S   (KELEMS / 2)               // f16x2 words per split array

__device__ int      g_mask_kind;           // 0 = uint8/bool, 1 = int32, 2 = float32
__device__ unsigned g_khi[KU32S];          // K fp16 hi  (f16x2-packed), built per launch
__device__ unsigned g_kmid[KU32S];         // K fp16 mid residual

// pack two fp32 -> f16x2 (lo = x, hi = y)
__device__ __forceinline__ unsigned pack_h2(float x, float y) {
    unsigned r;
    asm("cvt.rn.f16x2.f32 %0, %1, %2;" : "=r"(r) : "f"(y), "f"(x));
    return r;
}
// unpack f16x2 -> two fp32
__device__ __forceinline__ void unpack_h2(unsigned p, float& x, float& y) {
    asm("{ .reg .f16 l, h; mov.b32 {l, h}, %2; cvt.f32.f16 %0, l; cvt.f32.f16 %1, h; }"
        : "=f"(x), "=f"(y) : "r"(p));
}

// ---- prep: K fp16 hi/mid split (byte-neutral) + mask-dtype detection ----
__global__ void prep_kernel(const float* __restrict__ k, const unsigned char* __restrict__ m) {
    if (blockIdx.x == 0 && threadIdx.x < 32) {
        uint4 u = ((const uint4*)m)[threadIdx.x];   // 512 bytes sample
        unsigned fl = 0;
        #pragma unroll
        for (int bt = 0; bt < 4; ++bt) {
            unsigned uu = (&u.x)[bt];
            if (uu & 0x000000FFu) fl |= 1u;
            if (uu & 0x0000FF00u) fl |= 2u;
            if (uu & 0x00FF0000u) fl |= 4u;
            if (uu & 0xFF000000u) fl |= 8u;
        }
        fl = __reduce_or_sync(0xFFFFFFFFu, fl);
        if (threadIdx.x == 0) {
            int kind;
            if ((fl & 0xEu) == 0)                 kind = 1;  // int32
            else if ((fl & 1u) == 0 && (fl & 8u)) kind = 2;  // float32
            else                                  kind = 0;  // uint8 / bool
            g_mask_kind = kind;
        }
    }
    int i = blockIdx.x * 256 + threadIdx.x;        // float4 index
    float4 kv = ((const float4*)k)[i];
    unsigned hA = pack_h2(kv.x, kv.y);
    unsigned hB = pack_h2(kv.z, kv.w);
    float hx, hy, hz, hw;
    unpack_h2(hA, hx, hy);
    unpack_h2(hB, hz, hw);
    unsigned mA = pack_h2(kv.x - hx, kv.y - hy);
    unsigned mB = pack_h2(kv.z - hz, kv.w - hw);
    ((uint2*)g_khi)[i]  = make_uint2(hA, hB);
    ((uint2*)g_kmid)[i] = make_uint2(mA, mB);
}

__device__ __forceinline__ void mma_f16(float& d0, float& d1, float& d2, float& d3,
                                        unsigned a0, unsigned a1, unsigned a2, unsigned a3,
                                        unsigned b0, unsigned b1) {
    asm("mma.sync.aligned.m16n8k16.row.col.f32.f16.f16.f32 "
        "{%0,%1,%2,%3}, {%4,%5,%6,%7}, {%8,%9}, {%0,%1,%2,%3};"
        : "+f"(d0), "+f"(d1), "+f"(d2), "+f"(d3)
        : "r"(a0), "r"(a1), "r"(a2), "r"(a3), "r"(b0), "r"(b1));
}

__device__ __forceinline__ void ldsm_x4(unsigned& r0, unsigned& r1, unsigned& r2, unsigned& r3,
                                        unsigned saddr) {
    asm volatile("ldmatrix.sync.aligned.m8n8.x4.shared.b16 {%0,%1,%2,%3}, [%4];"
                 : "=r"(r0), "=r"(r1), "=r"(r2), "=r"(r3) : "r"(saddr));
}

__device__ __forceinline__ void cp_async16(unsigned dst, const void* src) {
    asm volatile("cp.async.cg.shared.global [%0], [%1], 16;" :: "r"(dst), "l"(src) : "memory");
}
__device__ __forceinline__ void cp_commit() {
    asm volatile("cp.async.commit_group;" ::: "memory");
}
__device__ __forceinline__ void cp_wait0() {
    asm volatile("cp.async.wait_group 0;" ::: "memory");
}
__device__ __forceinline__ void pair_bar(int id) {
    asm volatile("bar.sync %0, 64;" :: "r"(id) : "memory");
}

// load 4 mask flags for elements [basei, basei+4) of one score row
__device__ __forceinline__ void mask4(const unsigned char* mrow8, const unsigned* mrow32,
                                      int mkind, int basei,
                                      bool& m0, bool& m1, bool& m2, bool& m3) {
    if (mkind == 0) {
        unsigned mu = *(const unsigned*)(mrow8 + basei);
        m0 = (mu & 0x000000FFu) != 0; m1 = (mu & 0x0000FF00u) != 0;
        m2 = (mu & 0x00FF0000u) != 0; m3 = (mu & 0xFF000000u) != 0;
    } else {
        uint4 mu = *(const uint4*)(mrow32 + basei);
        m0 = mu.x != 0; m1 = mu.y != 0; m2 = mu.z != 0; m3 = mu.w != 0;
    }
}

// --------------------------------------------------------------------------
// One CTA = 16 q-rows of one batch, 512 threads / 16 warps.
// QK^T: fp16x2 3-term compensated MMA over per-warp-pair cp.async pipeline.
// Sparsemax: scan1 reads mask ONCE, packs per-lane validity into one 32-bit
// register bitmap; scan2/fallback test bits only. tau0-compaction stores
// (z,j) pairs -> iterations AND the V-gather list come from the same list.
// attn row = zero-fill + scatter. Gather: 8-way MLP batched V loads.
// --------------------------------------------------------------------------
extern "C" __global__ void __launch_bounds__(NTHR, 2)
sparse_attn_kernel(const float* __restrict__ q,
                   const float* __restrict__ v,
                   const void*  __restrict__ maskp,
                   float* __restrict__ out,
                   float* __restrict__ attn,
                   int write_attn)
{
    extern __shared__ float sm[];
    unsigned* khi_s = (unsigned*)sm;               // slot0; slot1 at +KMID_BYTE_OFF
    float*    sc    = sm + KS_FLOATS;              // [QT][SCP]

    const int tid  = threadIdx.x;
    const int w    = tid >> 5;
    const int lane = tid & 31;
    const int b    = blockIdx.y;
    const int q0   = blockIdx.x * QT;
    const int mkind = g_mask_kind;

    // ---- Q subtile (w>>3) as f16x2 B fragments (hi + mid), 16 regs ----
    unsigned bh0[4], bh1[4], bm0[4], bm1[4];
    {
        const float* qb = q + ((size_t)(b * LQ + q0 + 8 * (w >> 3) + (lane >> 2))) * DH + 2 * (lane & 3);
        #pragma unroll
        for (int ks = 0; ks < 4; ++ks) {
            float2 p0 = *(const float2*)(qb + ks * 16);
            float2 p1 = *(const float2*)(qb + ks * 16 + 8);
            float f0 = p0.x * TEMP_INV, f1 = p0.y * TEMP_INV;
            float f2 = p1.x * TEMP_INV, f3 = p1.y * TEMP_INV;
            bh0[ks] = pack_h2(f0, f1);
            bh1[ks] = pack_h2(f2, f3);
            float h0, h1, h2, h3;
            unpack_h2(bh0[ks], h0, h1);
            unpack_h2(bh1[ks], h2, h3);
            bm0[ks] = pack_h2(f0 - h0, f1 - h1);
            bm1[ks] = pack_h2(f2 - h2, f3 - h3);
        }
    }
    const int pair = w & 7;
    const int kr0  = 16 * pair;
    const int ti   = (w >> 3) * 32 + lane;         // 0..63 within pair

    const unsigned sm_shared = (unsigned)__cvta_generic_to_shared(khi_s);

    // ldmatrix per-lane address (shared space), ks advances by 32 bytes
    unsigned lm_base;
    {
        int g  = lane >> 3;                        // matrix index 0..3
        int rl = lane & 7;
        int row = kr0 + rl + 8 * (g & 1);          // m1/m3 -> rows +8
        lm_base = sm_shared + (unsigned)(row * KP32 * 4 + (g >> 1) * 16);   // m2/m3 -> k+8
    }

    // per-thread pair-slice copy addresses: 16 rows x 128B per unit, 2 cp16/thread
    unsigned cdst[2];
    int      csrc[2];
    #pragma unroll
    for (int i = 0; i < 2; ++i) {
        int flat = ti + 64 * i;
        int r = flat >> 3, c16 = flat & 7;
        cdst[i] = (unsigned)((kr0 + r) * KP32 * 4 + c16 * 16);
        csrc[i] = (kr0 + r) * 32 + c16 * 4;        // u32 offset within chunk base
    }

    // ---- QK^T per-pair pipeline over 16 units ----
    {
        {
            const unsigned* gsrc = g_khi + (size_t)(b * LK) * 32;
            cp_async16(sm_shared + cdst[0], gsrc + csrc[0]);
            cp_async16(sm_shared + cdst[1], gsrc + csrc[1]);
            cp_commit();
        }

        float d0 = 0.f, d1 = 0.f, d2 = 0.f, d3 = 0.f;
        for (int u = 0; u < NU; ++u) {
            cp_wait0();
            pair_bar(pair + 1);
            if (u + 1 < NU) {
                int cn = (u + 1) >> 1;
                const unsigned* gsrc = (((u + 1) & 1) ? g_kmid : g_khi)
                                       + (size_t)(b * LK + cn * CHUNK) * 32;
                unsigned dstb = sm_shared + ((u + 1) & 1) * KMID_BYTE_OFF;
                cp_async16(dstb + cdst[0], gsrc + csrc[0]);
                cp_async16(dstb + cdst[1], gsrc + csrc[1]);
                cp_commit();
            }
            if (!(u & 1)) {
                d0 = d1 = d2 = d3 = 0.f;
                #pragma unroll
                for (int ks = 0; ks < 4; ++ks) {
                    unsigned a0, a1, a2, a3;
                    ldsm_x4(a0, a1, a2, a3, lm_base + ks * 32);
                    mma_f16(d0, d1, d2, d3, a0, a1, a2, a3, bm0[ks], bm1[ks]);
                    mma_f16(d0, d1, d2, d3, a0, a1, a2, a3, bh0[ks], bh1[ks]);
                }
            } else {
                #pragma unroll
                for (int ks = 0; ks < 4; ++ks) {
                    unsigned a0, a1, a2, a3;
                    ldsm_x4(a0, a1, a2, a3, lm_base + KMID_BYTE_OFF + ks * 32);
                    mma_f16(d0, d1, d2, d3, a0, a1, a2, a3, bh0[ks], bh1[ks]);
                }
                int c  = u >> 1;
                int kg = c * CHUNK + kr0 + (lane >> 2);
                int qc = 8 * (w >> 3) + 2 * (lane & 3);
                sc[qc * SCP + kg]           = d0;
                sc[(qc + 1) * SCP + kg]     = d1;
                sc[qc * SCP + kg + 8]       = d2;
                sc[(qc + 1) * SCP + kg + 8] = d3;
            }
        }
    }
    __syncthreads();   // scores visible; K slots become per-warp scratch

    // ---- sparsemax (warp w owns row w); mask read ONCE into register bitmap ----
    const float* zr = sc + w * SCP;
    float* wsc = sm + w * WSCR;
    const unsigned lt = (1u << lane) - 1u;
    const size_t rowoff = (size_t)(b * LQ + q0 + w) * LK;
    const unsigned char* mrow8  = (const unsigned char*)maskp + rowoff;
    const unsigned*      mrow32 = (const unsigned*)maskp + rowoff;

    // scan1: S, C over unmasked entries; build validity bitmap (bit 4*t4+e = unmasked)
    unsigned vmask = 0;
    float S = 0.0f; int Cl = 0;
    #pragma unroll
    for (int t4 = 0; t4 < 8; ++t4) {
        int basei = 4 * lane + 128 * t4;
        float4 zv = *(const float4*)(zr + basei);
        bool m0, m1, m2, m3;
        mask4(mrow8, mrow32, mkind, basei, m0, m1, m2, m3);
        if (!m0) { S += zv.x; Cl++; vmask |= 1u << (4 * t4 + 0); }
        if (!m1) { S += zv.y; Cl++; vmask |= 1u << (4 * t4 + 1); }
        if (!m2) { S += zv.z; Cl++; vmask |= 1u << (4 * t4 + 2); }
        if (!m3) { S += zv.w; Cl++; vmask |= 1u << (4 * t4 + 3); }
    }
    #pragma unroll
    for (int o = 16; o; o >>= 1) S += __shfl_xor_sync(0xFFFFFFFFu, S, o);
    int C = __reduce_add_sync(0xFFFFFFFFu, Cl);

    float tau = 1.0e30f;
    int   cnt = 0;
    bool  listok = true;

    if (C > 0) {
        tau = (S - 1.0f) / (float)C;
        // scan2: compact (z, j) pairs with z > tau0, unmasked (bitmap test only)
        float s2 = 0.0f; int c2l = 0;
        #pragma unroll
        for (int t4 = 0; t4 < 8; ++t4) {
            int basei = 4 * lane + 128 * t4;
            float4 zv = *(const float4*)(zr + basei);
            #pragma unroll
            for (int e = 0; e < 4; ++e) {
                float z = (&zv.x)[e];
                bool a = ((vmask >> (4 * t4 + e)) & 1u) && z > tau;
                unsigned bb = __ballot_sync(0xFFFFFFFFu, a);
                if (a) {
                    int ps = cnt + __popc(bb & lt);
                    if (ps < CAPP) {
                        wsc[2 * ps]     = z;
                        wsc[2 * ps + 1] = __int_as_float(basei + e);
                    }
                    s2 += z; c2l++;
                }
                cnt += __popc(bb);
            }
        }
        int c2 = __reduce_add_sync(0xFFFFFFFFu, c2l);
        #pragma unroll
        for (int o = 16; o; o >>= 1) s2 += __shfl_xor_sync(0xFFFFFFFFu, s2, o);

        if (cnt <= CAPP) {
            if (c2 != C) {
                __syncwarp();
                S = s2; C = c2;
                tau = (S - 1.0f) / (float)C;
                for (int iter = 0; iter < 64; ++iter) {
                    float s3 = 0.0f; int c3l = 0;
                    for (int i = lane; i < cnt; i += 32) {
                        float2 e2 = *(const float2*)(wsc + 2 * i);
                        if (e2.x > tau) { s3 += e2.x; c3l++; }
                    }
                    int c3 = __reduce_add_sync(0xFFFFFFFFu, c3l);
                    #pragma unroll
                    for (int o = 16; o; o >>= 1) s3 += __shfl_xor_sync(0xFFFFFFFFu, s3, o);
                    if (c3 == C) break;
                    S = s3; C = c3;
                    tau = (S - 1.0f) / (float)C;
                }
            }
        } else {
            listok = false;
            if (c2 != C) {
                S = s2; C = c2;
                tau = (S - 1.0f) / (float)C;
                for (int iter = 0; iter < 64; ++iter) {
                    float s3 = 0.0f; int c3l = 0;
                    #pragma unroll
                    for (int t4 = 0; t4 < 8; ++t4) {
                        int basei = 4 * lane + 128 * t4;
                        float4 zv = *(const float4*)(zr + basei);
                        #pragma unroll
                        for (int e = 0; e < 4; ++e) {
                            float z = (&zv.x)[e];
                            if (((vmask >> (4 * t4 + e)) & 1u) && z > tau) { s3 += z; c3l++; }
                        }
                    }
                    int c3 = __reduce_add_sync(0xFFFFFFFFu, c3l);
                    #pragma unroll
                    for (int o = 16; o; o >>= 1) s3 += __shfl_xor_sync(0xFFFFFFFFu, s3, o);
                    if (c3 == C) break;
                    S = s3; C = c3;
                    tau = (S - 1.0f) / (float)C;
                }
            }
        }
    }
    __syncwarp();

    // ---- epilogue: attn row + sparse attn@V ----
    const float2* vb2 = (const float2*)(v + (size_t)b * LK * DH);
    float* arow = attn + rowoff;
    float2 acc2 = make_float2(0.0f, 0.0f);

    if (listok) {
        if (write_attn) {
            const float4 z4 = make_float4(0.f, 0.f, 0.f, 0.f);
            #pragma unroll
            for (int t = 0; t < 8; ++t)
                *(float4*)(arow + 4 * lane + 128 * t) = z4;
        }
        __syncwarp();   // zero-fill done before scatter

        // final support compaction (in-place) + attn scatter
        int ns = 0;
        for (int basei = 0; basei < cnt; basei += 32) {
            int i = basei + lane;
            float z = 0.f; int j = 0;
            bool valid = i < cnt;
            if (valid) {
                float2 e2 = *(const float2*)(wsc + 2 * i);
                z = e2.x; j = __float_as_int(e2.y);
            }
            float p = z - tau;
            bool a = valid && p > 0.0f;
            unsigned bb = __ballot_sync(0xFFFFFFFFu, a);
            __syncwarp();            // all reads of this chunk before in-place writes
            if (a) {
                int ps = ns + __popc(bb & lt);
                wsc[2 * ps]     = p;
                wsc[2 * ps + 1] = __int_as_float(j);
                if (write_attn) arow[j] = p;
            }
            ns += __popc(bb);
        }
        __syncwarp();

        // batched V gather: 8 independent loads in flight
        int i = 0;
        for (; i + 8 <= ns; i += 8) {
            float4 e0 = *(const float4*)(wsc + 2 * i);
            float4 e1 = *(const float4*)(wsc + 2 * i + 4);
            float4 e2 = *(const float4*)(wsc + 2 * i + 8);
            float4 e3 = *(const float4*)(wsc + 2 * i + 12);
            const float2 v0 = vb2[__float_as_int(e0.y) * 32 + lane];
            const float2 v1 = vb2[__float_as_int(e0.w) * 32 + lane];
            const float2 v2 = vb2[__float_as_int(e1.y) * 32 + lane];
            const float2 v3 = vb2[__float_as_int(e1.w) * 32 + lane];
            const float2 v4 = vb2[__float_as_int(e2.y) * 32 + lane];
            const float2 v5 = vb2[__float_as_int(e2.w) * 32 + lane];
            const float2 v6 = vb2[__float_as_int(e3.y) * 32 + lane];
            const float2 v7 = vb2[__float_as_int(e3.w) * 32 + lane];
            acc2.x += e0.x * v0.x;  acc2.y += e0.x * v0.y;
            acc2.x += e0.z * v1.x;  acc2.y += e0.z * v1.y;
            acc2.x += e1.x * v2.x;  acc2.y += e1.x * v2.y;
            acc2.x += e1.z * v3.x;  acc2.y += e1.z * v3.y;
            acc2.x += e2.x * v4.x;  acc2.y += e2.x * v4.y;
            acc2.x += e2.z * v5.x;  acc2.y += e2.z * v5.y;
            acc2.x += e3.x * v6.x;  acc2.y += e3.x * v6.y;
            acc2.x += e3.z * v7.x;  acc2.y += e3.z * v7.y;
        }
        for (; i + 4 <= ns; i += 4) {
            float4 e0 = *(const float4*)(wsc + 2 * i);
            float4 e1 = *(const float4*)(wsc + 2 * i + 4);
            const float2 v0 = vb2[__float_as_int(e0.y) * 32 + lane];
            const float2 v1 = vb2[__float_as_int(e0.w) * 32 + lane];
            const float2 v2 = vb2[__float_as_int(e1.y) * 32 + lane];
            const float2 v3 = vb2[__float_as_int(e1.w) * 32 + lane];
            acc2.x += e0.x * v0.x;  acc2.y += e0.x * v0.y;
            acc2.x += e0.z * v1.x;  acc2.y += e0.z * v1.y;
            acc2.x += e1.x * v2.x;  acc2.y += e1.x * v2.y;
            acc2.x += e1.z * v3.x;  acc2.y += e1.z * v3.y;
        }
        for (; i < ns; ++i) {
            float p = wsc[2 * i];
            int  j  = __float_as_int(wsc[2 * i + 1]);
            const float2 vv = vb2[j * 32 + lane];
            acc2.x += p * vv.x;
            acc2.y += p * vv.y;
        }
    } else {
        // fallback (rare, support@tau0 > CAPP): ballot-compaction p-pass, bitmap inline
        float* cp = wsc;
        int gcnt = 0;
        #pragma unroll
        for (int tt = 0; tt < 8; ++tt) {
            const int j0 = 4 * lane + 128 * tt;
            float4 zv = *(const float4*)(zr + j0);
            float4 pv;
            pv.x = ((vmask >> (4 * tt + 0)) & 1u) ? fmaxf(zv.x - tau, 0.0f) : 0.f;
            pv.y = ((vmask >> (4 * tt + 1)) & 1u) ? fmaxf(zv.y - tau, 0.0f) : 0.f;
            pv.z = ((vmask >> (4 * tt + 2)) & 1u) ? fmaxf(zv.z - tau, 0.0f) : 0.f;
            pv.w = ((vmask >> (4 * tt + 3)) & 1u) ? fmaxf(zv.w - tau, 0.0f) : 0.f;
            if (write_attn) *(float4*)(arow + j0) = pv;

            #pragma unroll
            for (int e = 0; e < 4; ++e) {
                float pe = (&pv.x)[e];
                bool a = pe > 0.0f;
                unsigned bb = __ballot_sync(0xFFFFFFFFu, a);
                int base = gcnt;
                if (a) {
                    int ps = base + __popc(bb & lt);
                    if (ps < CAPP) {
                        cp[2 * ps]     = pe;
                        cp[2 * ps + 1] = __int_as_float(j0 + e);
                    } else {
                        const float2 vv = vb2[(j0 + e) * 32 + lane];
                        acc2.x += pe * vv.x;
                        acc2.y += pe * vv.y;
                    }
                }
                gcnt += __popc(bb);
            }
        }
        __syncwarp();
        const int cn = gcnt < CAPP ? gcnt : CAPP;
        int i = 0;
        for (; i + 4 <= cn; i += 4) {
            float4 e0 = *(const float4*)(cp + 2 * i);
            float4 e1 = *(const float4*)(cp + 2 * i + 4);
            const float2 v0 = vb2[__float_as_int(e0.y) * 32 + lane];
            const float2 v1 = vb2[__float_as_int(e0.w) * 32 + lane];
            const float2 v2 = vb2[__float_as_int(e1.y) * 32 + lane];
            const float2 v3 = vb2[__float_as_int(e1.w) * 32 + lane];
            acc2.x += e0.x * v0.x;  acc2.y += e0.x * v0.y;
            acc2.x += e0.z * v1.x;  acc2.y += e0.z * v1.y;
            acc2.x += e1.x * v2.x;  acc2.y += e1.x * v2.y;
            acc2.x += e1.z * v3.x;  acc2.y += e1.z * v3.y;
        }
        for (; i < cn; ++i) {
            float p = cp[2 * i];
            int  j  = __float_as_int(cp[2 * i + 1]);
            const float2 vv = vb2[j * 32 + lane];
            acc2.x += p * vv.x;
            acc2.y += p * vv.y;
        }
    }

    *(float2*)(out + ((size_t)(b * LQ + q0 + w)) * DH + 2 * lane) = acc2;
}

// --------------------------------------------------------------------------
extern "C" void kernel_launch(void* const* d_in, const int* in_sizes, int n_in,
                              void* d_out, int out_size) {
    const float* q = (const float*)d_in[0];
    const float* k = (const float*)d_in[1];
    const float* v = (const float*)d_in[2];
    const void*  m = d_in[3];

    float* out = (float*)d_out;
    long long out_elems  = (long long)B_ * LQ * DH;
    long long attn_elems = (long long)B_ * LQ * LK;
    int write_attn = ((long long)out_size >= out_elems + attn_elems) ? 1 : 0;
    float* attn = out + (size_t)out_elems;

    prep_kernel<<<KELEMS / 4 / 256, 256>>>(k, (const unsigned char*)m);

    cudaFuncSetAttribute(sparse_attn_kernel,
                         cudaFuncAttributeMaxDynamicSharedMemorySize, SMEM_BYTES);

    dim3 grid(LQ / QT, B_);
    sparse_attn_kernel<<<grid, NTHR, SMEM_BYTES>>>(q, v, m, out, attn, write_attn);
}